// round 13
// baseline (speedup 1.0000x reference)
#include <cuda_runtime.h>
#include <cuda_bf16.h>
#include <cstdint>
#include <math.h>

#define N_NODES   20000
#define N_EDGES   640000
#define IN_CH     64
#define EDGE_DIM  16
#define HID       128
#define NLAYERS   3
#define NGRAPHS   128

typedef unsigned long long u64;

// ================= scratch (device globals) =================
__device__ float     g_h[2][N_NODES * HID];
__device__ float     g_P[N_NODES * HID];
__device__ float     g_R[N_NODES * HID];
__device__ float     g_wcomp[NLAYERS][HID * HID];
__device__ float     g_bvec[NLAYERS][HID];
__device__ float     g_deg[N_NODES];          // in-degree (by dst), for bvec
__device__ int       g_soff[N_NODES + 1];     // CSR row offsets by SRC
__device__ int       g_scur[N_NODES];         // counts, then fill cursors
__device__ int2      g_meta[N_EDGES];         // (dst, eid) per CSR slot
__device__ float     g_mean[NGRAPHS * HID];
__device__ unsigned  g_maxe[NGRAPHS * HID];
__device__ float     g_cnt[NGRAPHS];

__device__ __forceinline__ unsigned fenc(float f) {
    unsigned u = __float_as_uint(f);
    return (u & 0x80000000u) ? ~u : (u | 0x80000000u);
}
__device__ __forceinline__ float fdec(unsigned u) {
    return (u & 0x80000000u) ? __uint_as_float(u & 0x7FFFFFFFu)
                             : __uint_as_float(~u);
}
#define ENC_NEG_INF 0x007FFFFFu

// ---- packed f32x2 helpers ----
__device__ __forceinline__ u64 pk2(float lo, float hi) {
    u64 r; asm("mov.b64 %0, {%1, %2};" : "=l"(r) : "f"(lo), "f"(hi)); return r;
}
__device__ __forceinline__ void upk2(float& lo, float& hi, u64 v) {
    asm("mov.b64 {%0, %1}, %2;" : "=f"(lo), "=f"(hi) : "l"(v));
}
__device__ __forceinline__ void fma2(u64& d, u64 a, u64 b) {
    asm("fma.rn.f32x2 %0, %1, %2, %0;" : "+l"(d) : "l"(a), "l"(b));
}

// ======= init: zero deg, src counts, pool accum, cnt, R (one kernel) =======
__global__ void init_kernel() {
    int i = blockIdx.x * 256 + threadIdx.x;   // grid 2500
    reinterpret_cast<float4*>(g_R)[i] = make_float4(0.f, 0.f, 0.f, 0.f);
    if (i < N_NODES) { g_deg[i] = 0.f; g_scur[i] = 0; }
    if (i < NGRAPHS * HID) { g_mean[i] = 0.f; g_maxe[i] = ENC_NEG_INF; }
    if (i < NGRAPHS) g_cnt[i] = 0.f;
}

// ======= setup: dst-deg | src-count | graph-cnt | tiled compose ======
#define SETUP_DEG_BLKS  (N_EDGES / 256)                 // 2500
#define SETUP_SRC_BLKS  (N_EDGES / 256)                 // 2500
#define SETUP_CNT_BLKS  ((N_NODES + 255) / 256)         // 79
#define SETUP_CMP_BLKS  (NLAYERS * 4)                   // 12
#define SETUP_BLKS      (SETUP_DEG_BLKS + SETUP_SRC_BLKS + SETUP_CNT_BLKS + SETUP_CMP_BLKS)

__global__ void __launch_bounds__(256) setup_kernel(
    const int*   __restrict__ srcIdx,
    const int*   __restrict__ dstIdx,
    const int*   __restrict__ batch,
    const float* __restrict__ mw2,
    const float* __restrict__ uw,
    const float* __restrict__ mb2)
{
    const int blk = blockIdx.x;
    const int t   = threadIdx.x;

    if (blk < SETUP_DEG_BLKS) {
        int e = blk * 256 + t;
        atomicAdd(&g_deg[dstIdx[e]], 1.f);
        return;
    }
    if (blk < SETUP_DEG_BLKS + SETUP_SRC_BLKS) {
        int e = (blk - SETUP_DEG_BLKS) * 256 + t;
        atomicAdd(&g_scur[srcIdx[e]], 1);
        return;
    }
    if (blk < SETUP_DEG_BLKS + SETUP_SRC_BLKS + SETUP_CNT_BLKS) {
        int i = (blk - SETUP_DEG_BLKS - SETUP_SRC_BLKS) * 256 + t;
        if (i >= N_NODES) return;
        int g = batch[i];
        unsigned m = __match_any_sync(__activemask(), g);
        int leader = __ffs(m) - 1;
        if ((t & 31) == leader)
            atomicAdd(&g_cnt[g], (float)__popc(m));
        return;
    }

    const int cb   = blk - SETUP_DEG_BLKS - SETUP_SRC_BLKS - SETUP_CNT_BLKS;
    const int l    = cb >> 2;
    const int j0   = (cb & 3) * 32;
    const float* W2    = mw2 + (size_t)l * HID * HID;
    const float* WuBot = uw  + (size_t)l * 2 * HID * HID + (size_t)HID * HID;
    const float* b2    = mb2 + (size_t)l * HID;

    __shared__ float sA[32][17];
    __shared__ float sB[16][128];
    const int tx = t & 15;
    const int ty = t >> 4;
    const int col = tx * 8;

    float acc[2][8];
    #pragma unroll
    for (int i = 0; i < 2; i++)
        #pragma unroll
        for (int j = 0; j < 8; j++) acc[i][j] = 0.f;

    for (int kt = 0; kt < 8; kt++) {
        const int k0 = kt * 16;
        __syncthreads();
        #pragma unroll
        for (int q = 0; q < 2; q++) {
            int s = t * 2 + q;
            int r = s >> 4, c = s & 15;
            sA[r][c] = W2[(size_t)(j0 + r) * HID + k0 + c];
        }
        #pragma unroll
        for (int q = 0; q < 2; q++) {
            int s  = t * 2 + q;
            int kr = s >> 5;
            int c  = (s & 31) * 4;
            *reinterpret_cast<float4*>(&sB[kr][c]) =
                *reinterpret_cast<const float4*>(
                    WuBot + (size_t)(k0 + kr) * HID + c);
        }
        __syncthreads();
        #pragma unroll
        for (int k = 0; k < 16; k++) {
            float a0 = sA[ty*2][k], a1 = sA[ty*2 + 1][k];
            float4 b0 = *reinterpret_cast<float4*>(&sB[k][col]);
            float4 b1 = *reinterpret_cast<float4*>(&sB[k][col + 4]);
            float bb[8] = {b0.x,b0.y,b0.z,b0.w,b1.x,b1.y,b1.z,b1.w};
            #pragma unroll
            for (int j = 0; j < 8; j++) {
                acc[0][j] = fmaf(a0, bb[j], acc[0][j]);
                acc[1][j] = fmaf(a1, bb[j], acc[1][j]);
            }
        }
    }
    #pragma unroll
    for (int i = 0; i < 2; i++) {
        float* op = g_wcomp[l] + (size_t)(j0 + ty*2 + i) * HID + col;
        *reinterpret_cast<float4*>(op)     = make_float4(acc[i][0],acc[i][1],acc[i][2],acc[i][3]);
        *reinterpret_cast<float4*>(op + 4) = make_float4(acc[i][4],acc[i][5],acc[i][6],acc[i][7]);
    }
    if ((cb & 3) == 0 && t < HID) {
        float bv = 0.f;
        #pragma unroll 8
        for (int c = 0; c < HID; c++)
            bv = fmaf(b2[c], WuBot[(size_t)c * HID + t], bv);
        g_bvec[l][t] = bv;
    }
}

// ======= CSR scan (exclusive prefix of src counts) + fill =======
__global__ void scan_kernel() {
    __shared__ int warpSums[8];
    __shared__ int sTotal;
    const int t = threadIdx.x;
    const int lane = t & 31, warp = t >> 5;
    if (t == 0) sTotal = 0;
    __syncthreads();
    for (int base = 0; base < N_NODES; base += 256) {
        int i = base + t;
        int d = (i < N_NODES) ? g_scur[i] : 0;
        int v = d;
        #pragma unroll
        for (int o = 1; o < 32; o <<= 1) {
            int u = __shfl_up_sync(0xffffffffu, v, o);
            if (lane >= o) v += u;
        }
        if (lane == 31) warpSums[warp] = v;
        __syncthreads();
        if (warp == 0) {
            int ws = (lane < 8) ? warpSums[lane] : 0;
            #pragma unroll
            for (int o = 1; o < 8; o <<= 1) {
                int u = __shfl_up_sync(0xffffffffu, ws, o);
                if (lane >= o) ws += u;
            }
            if (lane < 8) warpSums[lane] = ws;
        }
        __syncthreads();
        int prefix = sTotal + (warp > 0 ? warpSums[warp - 1] : 0) + v - d;
        if (i < N_NODES) { g_soff[i] = prefix; g_scur[i] = prefix; }
        __syncthreads();
        if (t == 0) sTotal += warpSums[7];
        __syncthreads();
    }
    if (t == 0) g_soff[N_NODES] = sTotal;
}

__global__ void fill_kernel(const int* __restrict__ srcIdx,
                            const int* __restrict__ dstIdx) {
    int e = blockIdx.x * 256 + threadIdx.x;
    int s = srcIdx[e];
    int slot = atomicAdd(&g_scur[s], 1);
    g_meta[slot] = make_int2(dstIdx[e], e);
}

// ========== fused proj+pre: h0 = x@Wnp + bnp ; P = h0@W1 + b1 ==========
#define PP_OFF_SX 0
#define PP_OFF_SB 17408
#define PP_OFF_SH 25600
#define PP_SMEM   59392

__global__ void __launch_bounds__(256, 2) proj_pre_kernel(
    const float* __restrict__ x,
    const float* __restrict__ Wnp, const float* __restrict__ Bnp,
    const float* __restrict__ W1,  const float* __restrict__ B1)
{
    extern __shared__ char psm[];
    float (*sX)[68] = (float(*)[68])(psm + PP_OFF_SX);
    u64*   sB2      = (u64*)(psm + PP_OFF_SB);
    float* sH       = (float*)(psm + PP_OFF_SH);

    const int t  = threadIdx.x;
    const int n0 = blockIdx.x * 64;
    const int tx = t & 15;
    const int ty = t >> 4;
    const int col = tx * 8;

    #pragma unroll
    for (int r4 = 0; r4 < 4; r4++) {
        int idx = t + r4 * 256;
        int row = idx >> 4, c4 = (idx & 15) * 4;
        int n = n0 + row; if (n >= N_NODES) n = 0;
        float4 v = *reinterpret_cast<const float4*>(x + (size_t)n * IN_CH + c4);
        *reinterpret_cast<float4*>(&sX[row][c4]) = v;
    }

    u64 acc2[4][4];
    {
        float4 b0 = *reinterpret_cast<const float4*>(Bnp + col);
        float4 b1 = *reinterpret_cast<const float4*>(Bnp + col + 4);
        u64 bb[4] = {pk2(b0.x,b0.y), pk2(b0.z,b0.w), pk2(b1.x,b1.y), pk2(b1.z,b1.w)};
        #pragma unroll
        for (int i = 0; i < 4; i++)
            #pragma unroll
            for (int j = 0; j < 4; j++) acc2[i][j] = bb[j];
    }

    for (int kt = 0; kt < 4; kt++) {
        __syncthreads();
        #pragma unroll
        for (int q = 0; q < 2; q++) {
            int s  = t * 2 + q;
            int kr = s >> 5;
            int cf = (s & 31) * 4;
            float4 v = *reinterpret_cast<const float4*>(
                Wnp + (size_t)(kt * 16 + kr) * HID + cf);
            *reinterpret_cast<ulonglong2*>(&sB2[kr * 64 + (cf >> 1)]) =
                *reinterpret_cast<ulonglong2*>(&v);
        }
        __syncthreads();
        #pragma unroll
        for (int k = 0; k < 16; k++) {
            u64 a[4];
            #pragma unroll
            for (int i = 0; i < 4; i++) {
                float av = sX[ty*4 + i][kt*16 + k];
                a[i] = pk2(av, av);
            }
            ulonglong2 bA = *reinterpret_cast<ulonglong2*>(&sB2[k * 64 + tx*4]);
            ulonglong2 bB = *reinterpret_cast<ulonglong2*>(&sB2[k * 64 + tx*4 + 2]);
            #pragma unroll
            for (int i = 0; i < 4; i++) {
                fma2(acc2[i][0], a[i], bA.x);
                fma2(acc2[i][1], a[i], bA.y);
                fma2(acc2[i][2], a[i], bB.x);
                fma2(acc2[i][3], a[i], bB.y);
            }
        }
    }
    __syncthreads();

    #pragma unroll
    for (int i = 0; i < 4; i++) {
        float o[8];
        upk2(o[0],o[1],acc2[i][0]); upk2(o[2],o[3],acc2[i][1]);
        upk2(o[4],o[5],acc2[i][2]); upk2(o[6],o[7],acc2[i][3]);
        int n = n0 + ty*4 + i;
        float* sp = sH + (ty*4 + i) * 132 + col;
        *reinterpret_cast<float4*>(sp)     = make_float4(o[0],o[1],o[2],o[3]);
        *reinterpret_cast<float4*>(sp + 4) = make_float4(o[4],o[5],o[6],o[7]);
        if (n < N_NODES) {
            float* op = g_h[0] + (size_t)n * HID + col;
            *reinterpret_cast<float4*>(op)     = make_float4(o[0],o[1],o[2],o[3]);
            *reinterpret_cast<float4*>(op + 4) = make_float4(o[4],o[5],o[6],o[7]);
        }
    }

    {
        float4 b0 = *reinterpret_cast<const float4*>(B1 + col);
        float4 b1 = *reinterpret_cast<const float4*>(B1 + col + 4);
        u64 bb[4] = {pk2(b0.x,b0.y), pk2(b0.z,b0.w), pk2(b1.x,b1.y), pk2(b1.z,b1.w)};
        #pragma unroll
        for (int i = 0; i < 4; i++)
            #pragma unroll
            for (int j = 0; j < 4; j++) acc2[i][j] = bb[j];
    }
    for (int kt = 0; kt < 8; kt++) {
        __syncthreads();
        #pragma unroll
        for (int q = 0; q < 2; q++) {
            int s  = t * 2 + q;
            int kr = s >> 5;
            int cf = (s & 31) * 4;
            float4 v = *reinterpret_cast<const float4*>(
                W1 + (size_t)(kt * 16 + kr) * HID + cf);
            *reinterpret_cast<ulonglong2*>(&sB2[kr * 64 + (cf >> 1)]) =
                *reinterpret_cast<ulonglong2*>(&v);
        }
        __syncthreads();
        #pragma unroll
        for (int k = 0; k < 16; k++) {
            u64 a[4];
            #pragma unroll
            for (int i = 0; i < 4; i++) {
                float av = sH[(ty*4 + i) * 132 + kt*16 + k];
                a[i] = pk2(av, av);
            }
            ulonglong2 bA = *reinterpret_cast<ulonglong2*>(&sB2[k * 64 + tx*4]);
            ulonglong2 bB = *reinterpret_cast<ulonglong2*>(&sB2[k * 64 + tx*4 + 2]);
            #pragma unroll
            for (int i = 0; i < 4; i++) {
                fma2(acc2[i][0], a[i], bA.x);
                fma2(acc2[i][1], a[i], bA.y);
                fma2(acc2[i][2], a[i], bB.x);
                fma2(acc2[i][3], a[i], bB.y);
            }
        }
    }
    #pragma unroll
    for (int i = 0; i < 4; i++) {
        int n = n0 + ty*4 + i;
        if (n < N_NODES) {
            float o[8];
            upk2(o[0],o[1],acc2[i][0]); upk2(o[2],o[3],acc2[i][1]);
            upk2(o[4],o[5],acc2[i][2]); upk2(o[6],o[7],acc2[i][3]);
            float* op = g_P + (size_t)n * HID + col;
            *reinterpret_cast<float4*>(op)     = make_float4(o[0],o[1],o[2],o[3]);
            *reinterpret_cast<float4*>(op + 4) = make_float4(o[4],o[5],o[6],o[7]);
        }
    }
}

// ====== CSR-by-src edge kernel: one warp per source node ======
// P[src] loaded ONCE per node; per edge: uniform eattr LDG + red.v4 scatter.
__global__ void __launch_bounds__(256) edge_csr_kernel(
    const float* __restrict__ eattr,
    const float* __restrict__ W1e)
{
    const int t    = threadIdx.x;
    const int lane = t & 31;
    const int warp = t >> 5;
    const int n    = blockIdx.x * 8 + warp;     // grid 2500 * 8 = 20000

    u64 wlo[16], whi[16];
    #pragma unroll
    for (int k = 0; k < 16; k++) {
        float4 wv = *reinterpret_cast<const float4*>(
            W1e + (size_t)k * HID + lane * 4);
        wlo[k] = pk2(wv.x, wv.y);
        whi[k] = pk2(wv.z, wv.w);
    }

    const float4 p = *reinterpret_cast<const float4*>(
        g_P + (size_t)n * HID + lane * 4);
    const u64 p0 = pk2(p.x, p.y);
    const u64 p1 = pk2(p.z, p.w);

    const int beg = g_soff[n];
    const int end = g_soff[n + 1];

    for (int base = beg; base < end; base += 32) {
        const int cnt = min(32, end - base);
        int2 meta = (lane < cnt) ? g_meta[base + lane] : make_int2(0, 0);

        // prologue: eattr for edge 0 of this chunk
        int eid = __shfl_sync(0xffffffffu, meta.y, 0);
        const float4* ep = reinterpret_cast<const float4*>(
            eattr + (size_t)eid * EDGE_DIM);
        float4 e0 = ep[0], e1 = ep[1], e2 = ep[2], e3 = ep[3];

        for (int j = 0; j < cnt; j++) {
            float4 c0 = e0, c1 = e1, c2 = e2, c3 = e3;
            const int dst = __shfl_sync(0xffffffffu, meta.x, j);
            if (j + 1 < cnt) {                 // prefetch next edge's eattr
                int eidn = __shfl_sync(0xffffffffu, meta.y, j + 1);
                const float4* en = reinterpret_cast<const float4*>(
                    eattr + (size_t)eidn * EDGE_DIM);
                e0 = en[0]; e1 = en[1]; e2 = en[2]; e3 = en[3];
            }
            u64 ac0 = p0, ac1 = p1;
            float ka[16] = {c0.x,c0.y,c0.z,c0.w, c1.x,c1.y,c1.z,c1.w,
                            c2.x,c2.y,c2.z,c2.w, c3.x,c3.y,c3.z,c3.w};
            #pragma unroll
            for (int k = 0; k < 16; k++) {
                u64 av = pk2(ka[k], ka[k]);
                fma2(ac0, av, wlo[k]);
                fma2(ac1, av, whi[k]);
            }
            float r0, r1, r2, r3;
            upk2(r0, r1, ac0); upk2(r2, r3, ac1);
            r0 = fmaxf(r0, 0.f); r1 = fmaxf(r1, 0.f);
            r2 = fmaxf(r2, 0.f); r3 = fmaxf(r3, 0.f);
            float* rp = g_R + (size_t)dst * HID + lane * 4;
            asm volatile("red.global.add.v4.f32 [%0], {%1,%2,%3,%4};"
                         :: "l"(rp), "f"(r0), "f"(r1), "f"(r2), "f"(r3)
                         : "memory");
        }
    }
}

// ====== fused update (FFMA2 + double-buffered SMEM, 2 CTAs/SM) ======
#define UROWS     64
#define U_OFF_A2  0
#define U_OFF_B2  18432
#define U_OFF_SH  34816
#define U_OFF_DEG 68608
#define U_SMEM    68864
#define A2IDX(buf,r,k)  ((buf)*1152 + (r)*18 + (k))
#define B2IDX(buf,k,c2) ((buf)*1024 + (k)*64 + (c2))

__global__ void __launch_bounds__(256, 2) update_kernel(
    int ping, int layer,
    const float* __restrict__ Wtop,
    const float* __restrict__ B,
    const float* __restrict__ LG,
    const float* __restrict__ LB,
    const float* __restrict__ W1n,
    const float* __restrict__ B1n,
    const int*   __restrict__ batch,
    int hasNext)
{
    extern __shared__ char usm[];
    u64*   sA2  = (u64*)(usm + U_OFF_A2);
    u64*   sB2  = (u64*)(usm + U_OFF_B2);
    float* sH   = (float*)(usm + U_OFF_SH);
    float* sDeg = (float*)(usm + U_OFF_DEG);

    const float* __restrict__ h     = g_h[ping];
    float*       __restrict__ hout  = g_h[ping ^ 1];
    const float* __restrict__ wcomp = g_wcomp[layer];
    const int t  = threadIdx.x;
    const int n0 = blockIdx.x * UROWS;
    const int tx = t & 15;
    const int ty = t >> 4;
    const int col = tx * 8;

    const int aR = t >> 2, aC = (t & 3) * 4;
    int aN = n0 + aR; if (aN >= N_NODES) aN = 0;
    const int s0 = t * 2, s1 = t * 2 + 1;
    const int kr0 = s0 >> 5, cf0 = (s0 & 31) * 4;
    const int kr1 = s1 >> 5, cf1 = (s1 & 31) * 4;

    if (t < UROWS) {
        int n = n0 + t;
        sDeg[t] = (n < N_NODES) ? g_deg[n] : 0.f;
    }

    u64 acc2[4][4];
    {
        float4 b0 = *reinterpret_cast<const float4*>(B + col);
        float4 b1 = *reinterpret_cast<const float4*>(B + col + 4);
        u64 bb[4] = {pk2(b0.x,b0.y), pk2(b0.z,b0.w), pk2(b1.x,b1.y), pk2(b1.z,b1.w)};
        #pragma unroll
        for (int i = 0; i < 4; i++)
            #pragma unroll
            for (int j = 0; j < 4; j++) acc2[i][j] = bb[j];
    }

    {
        float4 vA = *reinterpret_cast<const float4*>(h + (size_t)aN * HID + aC);
        *reinterpret_cast<ulonglong2*>(&sA2[A2IDX(0, aR, aC)]) =
            make_ulonglong2(pk2(vA.x,vA.x), pk2(vA.y,vA.y));
        *reinterpret_cast<ulonglong2*>(&sA2[A2IDX(0, aR, aC + 2)]) =
            make_ulonglong2(pk2(vA.z,vA.z), pk2(vA.w,vA.w));
        float4 v0 = *reinterpret_cast<const float4*>(Wtop + (size_t)kr0 * HID + cf0);
        float4 v1 = *reinterpret_cast<const float4*>(Wtop + (size_t)kr1 * HID + cf1);
        *reinterpret_cast<ulonglong2*>(&sB2[B2IDX(0, kr0, cf0 >> 1)]) =
            *reinterpret_cast<ulonglong2*>(&v0);
        *reinterpret_cast<ulonglong2*>(&sB2[B2IDX(0, kr1, cf1 >> 1)]) =
            *reinterpret_cast<ulonglong2*>(&v1);
    }
    __syncthreads();

    for (int kt = 0; kt < 16; kt++) {
        const int cur = kt & 1, nxt = cur ^ 1;
        float4 rA, rB0, rB1;
        if (kt < 15) {
            const int k0 = (kt + 1) * 16;
            const float* ap = (k0 < 128)
                ? (h   + (size_t)aN * HID + k0 + aC)
                : (g_R + (size_t)aN * HID + (k0 - 128) + aC);
            rA = *reinterpret_cast<const float4*>(ap);
            const float* w0 = (k0 < 128)
                ? (Wtop  + (size_t)(k0 + kr0) * HID + cf0)
                : (wcomp + (size_t)(k0 - 128 + kr0) * HID + cf0);
            const float* w1 = (k0 < 128)
                ? (Wtop  + (size_t)(k0 + kr1) * HID + cf1)
                : (wcomp + (size_t)(k0 - 128 + kr1) * HID + cf1);
            rB0 = *reinterpret_cast<const float4*>(w0);
            rB1 = *reinterpret_cast<const float4*>(w1);
        }
        #pragma unroll
        for (int k = 0; k < 16; k++) {
            u64 a[4];
            #pragma unroll
            for (int i = 0; i < 4; i++)
                a[i] = sA2[A2IDX(cur, ty*4 + i, k)];
            ulonglong2 bA = *reinterpret_cast<ulonglong2*>(&sB2[B2IDX(cur, k, tx*4)]);
            ulonglong2 bB = *reinterpret_cast<ulonglong2*>(&sB2[B2IDX(cur, k, tx*4 + 2)]);
            #pragma unroll
            for (int i = 0; i < 4; i++) {
                fma2(acc2[i][0], a[i], bA.x);
                fma2(acc2[i][1], a[i], bA.y);
                fma2(acc2[i][2], a[i], bB.x);
                fma2(acc2[i][3], a[i], bB.y);
            }
        }
        if (kt < 15) {
            *reinterpret_cast<ulonglong2*>(&sA2[A2IDX(nxt, aR, aC)]) =
                make_ulonglong2(pk2(rA.x,rA.x), pk2(rA.y,rA.y));
            *reinterpret_cast<ulonglong2*>(&sA2[A2IDX(nxt, aR, aC + 2)]) =
                make_ulonglong2(pk2(rA.z,rA.z), pk2(rA.w,rA.w));
            *reinterpret_cast<ulonglong2*>(&sB2[B2IDX(nxt, kr0, cf0 >> 1)]) =
                *reinterpret_cast<ulonglong2*>(&rB0);
            *reinterpret_cast<ulonglong2*>(&sB2[B2IDX(nxt, kr1, cf1 >> 1)]) =
                *reinterpret_cast<ulonglong2*>(&rB1);
        }
        __syncthreads();
    }

    float4 g0  = *reinterpret_cast<const float4*>(LG + col);
    float4 g1  = *reinterpret_cast<const float4*>(LG + col + 4);
    float4 lb0 = *reinterpret_cast<const float4*>(LB + col);
    float4 lb1 = *reinterpret_cast<const float4*>(LB + col + 4);
    float4 bv0 = *reinterpret_cast<const float4*>(g_bvec[layer] + col);
    float4 bv1 = *reinterpret_cast<const float4*>(g_bvec[layer] + col + 4);
    float gg[8]  = {g0.x,g0.y,g0.z,g0.w,g1.x,g1.y,g1.z,g1.w};
    float lbv[8] = {lb0.x,lb0.y,lb0.z,lb0.w,lb1.x,lb1.y,lb1.z,lb1.w};
    float bvv[8] = {bv0.x,bv0.y,bv0.z,bv0.w,bv1.x,bv1.y,bv1.z,bv1.w};

    #pragma unroll
    for (int i = 0; i < 4; i++) {
        float acc[8];
        upk2(acc[0],acc[1],acc2[i][0]); upk2(acc[2],acc[3],acc2[i][1]);
        upk2(acc[4],acc[5],acc2[i][2]); upk2(acc[6],acc[7],acc2[i][3]);
        float dg = sDeg[ty * 4 + i];
        float s = 0.f, q = 0.f;
        #pragma unroll
        for (int j = 0; j < 8; j++) {
            acc[j] = fmaxf(acc[j] + dg * bvv[j], 0.f);
            s += acc[j]; q += acc[j] * acc[j];
        }
        #pragma unroll
        for (int m = 1; m < 16; m <<= 1) {
            s += __shfl_xor_sync(0xffffffffu, s, m);
            q += __shfl_xor_sync(0xffffffffu, q, m);
        }
        float mu  = s * (1.f / 128.f);
        float var = q * (1.f / 128.f) - mu * mu;
        float rs  = rsqrtf(var + 1e-5f);

        int n = n0 + ty * 4 + i;
        if (n < N_NODES) {
            const float* rp = h + (size_t)n * HID + col;
            float4 r0 = *reinterpret_cast<const float4*>(rp);
            float4 r1 = *reinterpret_cast<const float4*>(rp + 4);
            float rr[8] = {r0.x,r0.y,r0.z,r0.w,r1.x,r1.y,r1.z,r1.w};
            float o[8];
            #pragma unroll
            for (int j = 0; j < 8; j++) {
                float v = (acc[j] - mu) * rs * gg[j] + lbv[j];
                o[j] = fmaxf(v, 0.f) + rr[j];
            }
            if (hasNext) {
                float* sp = sH + (ty*4 + i) * 132 + col;
                *reinterpret_cast<float4*>(sp)     = make_float4(o[0],o[1],o[2],o[3]);
                *reinterpret_cast<float4*>(sp + 4) = make_float4(o[4],o[5],o[6],o[7]);
                float* op = hout + (size_t)n * HID + col;
                *reinterpret_cast<float4*>(op)     = make_float4(o[0],o[1],o[2],o[3]);
                *reinterpret_cast<float4*>(op + 4) = make_float4(o[4],o[5],o[6],o[7]);
            } else {
                int gph = batch[n];
                #pragma unroll
                for (int j = 0; j < 8; j++) {
                    atomicAdd(&g_mean[gph * HID + col + j], o[j]);
                    atomicMax(&g_maxe[gph * HID + col + j], fenc(o[j]));
                }
            }
        }
    }

    {
        float4 z = make_float4(0.f, 0.f, 0.f, 0.f);
        #pragma unroll
        for (int qq = 0; qq < 8; qq++) {
            int idx = qq * 256 + t;
            int n = n0 + (idx >> 5);
            if (n < N_NODES)
                reinterpret_cast<float4*>(g_R + (size_t)n * HID)[idx & 31] = z;
        }
    }

    if (!hasNext) return;

    {
        float4 b0 = *reinterpret_cast<const float4*>(B1n + col);
        float4 b1 = *reinterpret_cast<const float4*>(B1n + col + 4);
        u64 bb[4] = {pk2(b0.x,b0.y), pk2(b0.z,b0.w), pk2(b1.x,b1.y), pk2(b1.z,b1.w)};
        #pragma unroll
        for (int i = 0; i < 4; i++)
            #pragma unroll
            for (int j = 0; j < 4; j++) acc2[i][j] = bb[j];
    }
    {
        float4 v0 = *reinterpret_cast<const float4*>(W1n + (size_t)kr0 * HID + cf0);
        float4 v1 = *reinterpret_cast<const float4*>(W1n + (size_t)kr1 * HID + cf1);
        *reinterpret_cast<ulonglong2*>(&sB2[B2IDX(0, kr0, cf0 >> 1)]) =
            *reinterpret_cast<ulonglong2*>(&v0);
        *reinterpret_cast<ulonglong2*>(&sB2[B2IDX(0, kr1, cf1 >> 1)]) =
            *reinterpret_cast<ulonglong2*>(&v1);
    }
    __syncthreads();
    for (int kt = 0; kt < 8; kt++) {
        const int cur = kt & 1, nxt = cur ^ 1;
        float4 rB0, rB1;
        if (kt < 7) {
            const int k0 = (kt + 1) * 16;
            rB0 = *reinterpret_cast<const float4*>(W1n + (size_t)(k0 + kr0) * HID + cf0);
            rB1 = *reinterpret_cast<const float4*>(W1n + (size_t)(k0 + kr1) * HID + cf1);
        }
        #pragma unroll
        for (int k = 0; k < 16; k++) {
            u64 a[4];
            #pragma unroll
            for (int i = 0; i < 4; i++) {
                float av = sH[(ty*4 + i) * 132 + kt*16 + k];
                a[i] = pk2(av, av);
            }
            ulonglong2 bA = *reinterpret_cast<ulonglong2*>(&sB2[B2IDX(cur, k, tx*4)]);
            ulonglong2 bB = *reinterpret_cast<ulonglong2*>(&sB2[B2IDX(cur, k, tx*4 + 2)]);
            #pragma unroll
            for (int i = 0; i < 4; i++) {
                fma2(acc2[i][0], a[i], bA.x);
                fma2(acc2[i][1], a[i], bA.y);
                fma2(acc2[i][2], a[i], bB.x);
                fma2(acc2[i][3], a[i], bB.y);
            }
        }
        if (kt < 7) {
            *reinterpret_cast<ulonglong2*>(&sB2[B2IDX(nxt, kr0, cf0 >> 1)]) =
                *reinterpret_cast<ulonglong2*>(&rB0);
            *reinterpret_cast<ulonglong2*>(&sB2[B2IDX(nxt, kr1, cf1 >> 1)]) =
                *reinterpret_cast<ulonglong2*>(&rB1);
        }
        __syncthreads();
    }
    #pragma unroll
    for (int i = 0; i < 4; i++) {
        int n = n0 + ty * 4 + i;
        if (n < N_NODES) {
            float o[8];
            upk2(o[0],o[1],acc2[i][0]); upk2(o[2],o[3],acc2[i][1]);
            upk2(o[4],o[5],acc2[i][2]); upk2(o[6],o[7],acc2[i][3]);
            float* op = g_P + (size_t)n * HID + col;
            *reinterpret_cast<float4*>(op)     = make_float4(o[0],o[1],o[2],o[3]);
            *reinterpret_cast<float4*>(op + 4) = make_float4(o[4],o[5],o[6],o[7]);
        }
    }
}

// ================= readout =================
__global__ void readout_kernel(const float* __restrict__ W1,
                               const float* __restrict__ B1,
                               const float* __restrict__ W2,
                               const float* __restrict__ B2,
                               float* __restrict__ out)
{
    __shared__ float gv[256];
    __shared__ float red[128];
    const int g = blockIdx.x, t = threadIdx.x;
    float cnt = fmaxf(g_cnt[g], 1.f);
    gv[t]       = g_mean[g * HID + t] / cnt;
    gv[128 + t] = fdec(g_maxe[g * HID + t]);
    __syncthreads();
    float a = B1[t];
    #pragma unroll 8
    for (int k = 0; k < 256; k++)
        a = fmaf(gv[k], W1[(size_t)k * HID + t], a);
    a = fmaxf(a, 0.f) * W2[t];
    red[t] = a;
    __syncthreads();
    for (int s2 = 64; s2 > 0; s2 >>= 1) {
        if (t < s2) red[t] += red[t + s2];
        __syncthreads();
    }
    if (t == 0) out[g] = red[0] + B2[0];
}

// ================= launch =================
extern "C" void kernel_launch(void* const* d_in, const int* in_sizes, int n_in,
                              void* d_out, int out_size)
{
    const float* x     = (const float*)d_in[0];
    const int*   ei    = (const int*)  d_in[1];
    const float* eattr = (const float*)d_in[2];
    const int*   batch = (const int*)  d_in[3];
    const float* npw   = (const float*)d_in[4];
    const float* npb   = (const float*)d_in[5];
    const float* mw1   = (const float*)d_in[6];
    const float* mb1   = (const float*)d_in[7];
    const float* mw2   = (const float*)d_in[8];
    const float* mb2   = (const float*)d_in[9];
    const float* uw    = (const float*)d_in[10];
    const float* ub    = (const float*)d_in[11];
    const float* lg    = (const float*)d_in[12];
    const float* lb    = (const float*)d_in[13];
    const float* fw1   = (const float*)d_in[14];
    const float* fb1   = (const float*)d_in[15];
    const float* fw2   = (const float*)d_in[16];
    const float* fb2   = (const float*)d_in[17];
    float* out = (float*)d_out;

    const int* srcIdx = ei;
    const int* dstIdx = ei + N_EDGES;

    cudaFuncSetAttribute(update_kernel,
                         cudaFuncAttributeMaxDynamicSharedMemorySize, U_SMEM);
    cudaFuncSetAttribute(proj_pre_kernel,
                         cudaFuncAttributeMaxDynamicSharedMemorySize, PP_SMEM);

    init_kernel<<<(N_NODES * HID / 4) / 256, 256>>>();
    setup_kernel<<<SETUP_BLKS, 256>>>(srcIdx, dstIdx, batch, mw2, uw, mb2);
    scan_kernel<<<1, 256>>>();
    fill_kernel<<<N_EDGES / 256, 256>>>(srcIdx, dstIdx);
    proj_pre_kernel<<<(N_NODES + 63) / 64, 256, PP_SMEM>>>(x, npw, npb, mw1, mb1);

    int ping = 0;
    for (int l = 0; l < NLAYERS; l++) {
        const float* W1l  = mw1 + (size_t)l * (HID + EDGE_DIM) * HID;
        const float* W1el = W1l + (size_t)HID * HID;
        const float* Wul  = uw  + (size_t)l * 2 * HID * HID;
        const int hasNext = (l + 1 < NLAYERS);
        const float* W1n  = hasNext ? (W1l + (size_t)(HID + EDGE_DIM) * HID) : W1l;
        const float* B1n  = hasNext ? (mb1 + (size_t)(l + 1) * HID) : mb1;

        edge_csr_kernel<<<N_NODES / 8, 256>>>(eattr, W1el);
        update_kernel<<<(N_NODES + UROWS - 1) / UROWS, 256, U_SMEM>>>(
            ping, l, Wul, ub + (size_t)l * HID,
            lg + (size_t)l * HID, lb + (size_t)l * HID,
            W1n, B1n, batch, hasNext);
        ping ^= 1;
    }

    readout_kernel<<<NGRAPHS, 128>>>(fw1, fb1, fw2, fb2, out);
}

// round 14
// speedup vs baseline: 1.3561x; 1.3561x over previous
#include <cuda_runtime.h>
#include <cuda_bf16.h>
#include <cstdint>
#include <math.h>

#define N_NODES   20000
#define N_EDGES   640000
#define IN_CH     64
#define EDGE_DIM  16
#define HID       128
#define NLAYERS   3
#define NGRAPHS   128
#define ETILE     256
#define N_ETILES  (N_EDGES / ETILE)   // 2500

typedef unsigned long long u64;

// ================= scratch (device globals) =================
__device__ float     g_h[2][N_NODES * HID];
__device__ float     g_P[N_NODES * HID];
__device__ float     g_R[N_NODES * HID];
__device__ float     g_wcomp[NLAYERS][HID * HID];
__device__ float     g_bvec[NLAYERS][HID];
__device__ float     g_deg[N_NODES];
__device__ float     g_mean[NGRAPHS * HID];
__device__ unsigned  g_maxe[NGRAPHS * HID];
__device__ float     g_cnt[NGRAPHS];

__device__ __forceinline__ unsigned fenc(float f) {
    unsigned u = __float_as_uint(f);
    return (u & 0x80000000u) ? ~u : (u | 0x80000000u);
}
__device__ __forceinline__ float fdec(unsigned u) {
    return (u & 0x80000000u) ? __uint_as_float(u & 0x7FFFFFFFu)
                             : __uint_as_float(~u);
}
#define ENC_NEG_INF 0x007FFFFFu

// ---- packed f32x2 helpers ----
__device__ __forceinline__ u64 pk2(float lo, float hi) {
    u64 r; asm("mov.b64 %0, {%1, %2};" : "=l"(r) : "f"(lo), "f"(hi)); return r;
}
__device__ __forceinline__ void upk2(float& lo, float& hi, u64 v) {
    asm("mov.b64 {%0, %1}, %2;" : "=f"(lo), "=f"(hi) : "l"(v));
}
__device__ __forceinline__ void fma2(u64& d, u64 a, u64 b) {
    asm("fma.rn.f32x2 %0, %1, %2, %0;" : "+l"(d) : "l"(a), "l"(b));
}

// ======= init: zero deg, pool accum, cnt, R (one kernel) =======
__global__ void init_kernel() {
    int i = blockIdx.x * 256 + threadIdx.x;   // grid 2500
    reinterpret_cast<float4*>(g_R)[i] = make_float4(0.f, 0.f, 0.f, 0.f);
    if (i < N_NODES) g_deg[i] = 0.f;
    if (i < NGRAPHS * HID) { g_mean[i] = 0.f; g_maxe[i] = ENC_NEG_INF; }
    if (i < NGRAPHS) g_cnt[i] = 0.f;
}

// ======= setup: deg count | cnt count | tiled compose (block ranges) ======
#define SETUP_DEG_BLKS  (N_EDGES / 256)                 // 2500
#define SETUP_CNT_BLKS  ((N_NODES + 255) / 256)         // 79
#define SETUP_CMP_BLKS  (NLAYERS * 4)                   // 12
#define SETUP_BLKS      (SETUP_DEG_BLKS + SETUP_CNT_BLKS + SETUP_CMP_BLKS)

__global__ void __launch_bounds__(256) setup_kernel(
    const int*   __restrict__ dstIdx,
    const int*   __restrict__ batch,
    const float* __restrict__ mw2,
    const float* __restrict__ uw,
    const float* __restrict__ mb2)
{
    const int blk = blockIdx.x;
    const int t   = threadIdx.x;

    if (blk < SETUP_DEG_BLKS) {
        int e = blk * 256 + t;
        atomicAdd(&g_deg[dstIdx[e]], 1.f);
        return;
    }
    if (blk < SETUP_DEG_BLKS + SETUP_CNT_BLKS) {
        int i = (blk - SETUP_DEG_BLKS) * 256 + t;
        if (i >= N_NODES) return;
        int g = batch[i];
        unsigned m = __match_any_sync(__activemask(), g);
        int leader = __ffs(m) - 1;
        if ((t & 31) == leader)
            atomicAdd(&g_cnt[g], (float)__popc(m));
        return;
    }

    const int cb   = blk - SETUP_DEG_BLKS - SETUP_CNT_BLKS;
    const int l    = cb >> 2;
    const int j0   = (cb & 3) * 32;
    const float* W2    = mw2 + (size_t)l * HID * HID;
    const float* WuBot = uw  + (size_t)l * 2 * HID * HID + (size_t)HID * HID;
    const float* b2    = mb2 + (size_t)l * HID;

    __shared__ float sA[32][17];
    __shared__ float sB[16][128];
    const int tx = t & 15;
    const int ty = t >> 4;
    const int col = tx * 8;

    float acc[2][8];
    #pragma unroll
    for (int i = 0; i < 2; i++)
        #pragma unroll
        for (int j = 0; j < 8; j++) acc[i][j] = 0.f;

    for (int kt = 0; kt < 8; kt++) {
        const int k0 = kt * 16;
        __syncthreads();
        #pragma unroll
        for (int q = 0; q < 2; q++) {
            int s = t * 2 + q;
            int r = s >> 4, c = s & 15;
            sA[r][c] = W2[(size_t)(j0 + r) * HID + k0 + c];
        }
        #pragma unroll
        for (int q = 0; q < 2; q++) {
            int s  = t * 2 + q;
            int kr = s >> 5;
            int c  = (s & 31) * 4;
            *reinterpret_cast<float4*>(&sB[kr][c]) =
                *reinterpret_cast<const float4*>(
                    WuBot + (size_t)(k0 + kr) * HID + c);
        }
        __syncthreads();
        #pragma unroll
        for (int k = 0; k < 16; k++) {
            float a0 = sA[ty*2][k], a1 = sA[ty*2 + 1][k];
            float4 b0 = *reinterpret_cast<float4*>(&sB[k][col]);
            float4 b1 = *reinterpret_cast<float4*>(&sB[k][col + 4]);
            float bb[8] = {b0.x,b0.y,b0.z,b0.w,b1.x,b1.y,b1.z,b1.w};
            #pragma unroll
            for (int j = 0; j < 8; j++) {
                acc[0][j] = fmaf(a0, bb[j], acc[0][j]);
                acc[1][j] = fmaf(a1, bb[j], acc[1][j]);
            }
        }
    }
    #pragma unroll
    for (int i = 0; i < 2; i++) {
        float* op = g_wcomp[l] + (size_t)(j0 + ty*2 + i) * HID + col;
        *reinterpret_cast<float4*>(op)     = make_float4(acc[i][0],acc[i][1],acc[i][2],acc[i][3]);
        *reinterpret_cast<float4*>(op + 4) = make_float4(acc[i][4],acc[i][5],acc[i][6],acc[i][7]);
    }
    if ((cb & 3) == 0 && t < HID) {
        float bv = 0.f;
        #pragma unroll 8
        for (int c = 0; c < HID; c++)
            bv = fmaf(b2[c], WuBot[(size_t)c * HID + t], bv);
        g_bvec[l][t] = bv;
    }
}

// ========== fused proj+pre: h0 = x@Wnp + bnp ; P = h0@W1 + b1 ==========
#define PP_OFF_SX 0                       // 64*68*4  = 17408
#define PP_OFF_SB 17408                   // u64 16*64*8 = 8192
#define PP_OFF_SH 25600                   // 64*132*4 = 33792
#define PP_SMEM   59392

__global__ void __launch_bounds__(256, 2) proj_pre_kernel(
    const float* __restrict__ x,
    const float* __restrict__ Wnp, const float* __restrict__ Bnp,
    const float* __restrict__ W1,  const float* __restrict__ B1)
{
    extern __shared__ char psm[];
    float (*sX)[68] = (float(*)[68])(psm + PP_OFF_SX);
    u64*   sB2      = (u64*)(psm + PP_OFF_SB);
    float* sH       = (float*)(psm + PP_OFF_SH);

    const int t  = threadIdx.x;
    const int n0 = blockIdx.x * 64;
    const int tx = t & 15;
    const int ty = t >> 4;
    const int col = tx * 8;

    #pragma unroll
    for (int r4 = 0; r4 < 4; r4++) {
        int idx = t + r4 * 256;
        int row = idx >> 4, c4 = (idx & 15) * 4;
        int n = n0 + row; if (n >= N_NODES) n = 0;
        float4 v = *reinterpret_cast<const float4*>(x + (size_t)n * IN_CH + c4);
        *reinterpret_cast<float4*>(&sX[row][c4]) = v;
    }

    u64 acc2[4][4];
    {
        float4 b0 = *reinterpret_cast<const float4*>(Bnp + col);
        float4 b1 = *reinterpret_cast<const float4*>(Bnp + col + 4);
        u64 bb[4] = {pk2(b0.x,b0.y), pk2(b0.z,b0.w), pk2(b1.x,b1.y), pk2(b1.z,b1.w)};
        #pragma unroll
        for (int i = 0; i < 4; i++)
            #pragma unroll
            for (int j = 0; j < 4; j++) acc2[i][j] = bb[j];
    }

    for (int kt = 0; kt < 4; kt++) {
        __syncthreads();
        #pragma unroll
        for (int q = 0; q < 2; q++) {
            int s  = t * 2 + q;
            int kr = s >> 5;
            int cf = (s & 31) * 4;
            float4 v = *reinterpret_cast<const float4*>(
                Wnp + (size_t)(kt * 16 + kr) * HID + cf);
            *reinterpret_cast<ulonglong2*>(&sB2[kr * 64 + (cf >> 1)]) =
                *reinterpret_cast<ulonglong2*>(&v);
        }
        __syncthreads();
        #pragma unroll
        for (int k = 0; k < 16; k++) {
            u64 a[4];
            #pragma unroll
            for (int i = 0; i < 4; i++) {
                float av = sX[ty*4 + i][kt*16 + k];
                a[i] = pk2(av, av);
            }
            ulonglong2 bA = *reinterpret_cast<ulonglong2*>(&sB2[k * 64 + tx*4]);
            ulonglong2 bB = *reinterpret_cast<ulonglong2*>(&sB2[k * 64 + tx*4 + 2]);
            #pragma unroll
            for (int i = 0; i < 4; i++) {
                fma2(acc2[i][0], a[i], bA.x);
                fma2(acc2[i][1], a[i], bA.y);
                fma2(acc2[i][2], a[i], bB.x);
                fma2(acc2[i][3], a[i], bB.y);
            }
        }
    }
    __syncthreads();

    #pragma unroll
    for (int i = 0; i < 4; i++) {
        float o[8];
        upk2(o[0],o[1],acc2[i][0]); upk2(o[2],o[3],acc2[i][1]);
        upk2(o[4],o[5],acc2[i][2]); upk2(o[6],o[7],acc2[i][3]);
        int n = n0 + ty*4 + i;
        float* sp = sH + (ty*4 + i) * 132 + col;
        *reinterpret_cast<float4*>(sp)     = make_float4(o[0],o[1],o[2],o[3]);
        *reinterpret_cast<float4*>(sp + 4) = make_float4(o[4],o[5],o[6],o[7]);
        if (n < N_NODES) {
            float* op = g_h[0] + (size_t)n * HID + col;
            *reinterpret_cast<float4*>(op)     = make_float4(o[0],o[1],o[2],o[3]);
            *reinterpret_cast<float4*>(op + 4) = make_float4(o[4],o[5],o[6],o[7]);
        }
    }

    {
        float4 b0 = *reinterpret_cast<const float4*>(B1 + col);
        float4 b1 = *reinterpret_cast<const float4*>(B1 + col + 4);
        u64 bb[4] = {pk2(b0.x,b0.y), pk2(b0.z,b0.w), pk2(b1.x,b1.y), pk2(b1.z,b1.w)};
        #pragma unroll
        for (int i = 0; i < 4; i++)
            #pragma unroll
            for (int j = 0; j < 4; j++) acc2[i][j] = bb[j];
    }
    for (int kt = 0; kt < 8; kt++) {
        __syncthreads();
        #pragma unroll
        for (int q = 0; q < 2; q++) {
            int s  = t * 2 + q;
            int kr = s >> 5;
            int cf = (s & 31) * 4;
            float4 v = *reinterpret_cast<const float4*>(
                W1 + (size_t)(kt * 16 + kr) * HID + cf);
            *reinterpret_cast<ulonglong2*>(&sB2[kr * 64 + (cf >> 1)]) =
                *reinterpret_cast<ulonglong2*>(&v);
        }
        __syncthreads();
        #pragma unroll
        for (int k = 0; k < 16; k++) {
            u64 a[4];
            #pragma unroll
            for (int i = 0; i < 4; i++) {
                float av = sH[(ty*4 + i) * 132 + kt*16 + k];
                a[i] = pk2(av, av);
            }
            ulonglong2 bA = *reinterpret_cast<ulonglong2*>(&sB2[k * 64 + tx*4]);
            ulonglong2 bB = *reinterpret_cast<ulonglong2*>(&sB2[k * 64 + tx*4 + 2]);
            #pragma unroll
            for (int i = 0; i < 4; i++) {
                fma2(acc2[i][0], a[i], bA.x);
                fma2(acc2[i][1], a[i], bA.y);
                fma2(acc2[i][2], a[i], bB.x);
                fma2(acc2[i][3], a[i], bB.y);
            }
        }
    }
    #pragma unroll
    for (int i = 0; i < 4; i++) {
        int n = n0 + ty*4 + i;
        if (n < N_NODES) {
            float o[8];
            upk2(o[0],o[1],acc2[i][0]); upk2(o[2],o[3],acc2[i][1]);
            upk2(o[4],o[5],acc2[i][2]); upk2(o[6],o[7],acc2[i][3]);
            float* op = g_P + (size_t)n * HID + col;
            *reinterpret_cast<float4*>(op)     = make_float4(o[0],o[1],o[2],o[3]);
            *reinterpret_cast<float4*>(op + 4) = make_float4(o[4],o[5],o[6],o[7]);
        }
    }
}

// ================= edge kernel: plain-float4 eattr tile (round-12 best) ====
__global__ void __launch_bounds__(256) edge_kernel(
    const float* __restrict__ eattr,
    const int*   __restrict__ srcIdx,
    const int*   __restrict__ dstIdx,
    const float* __restrict__ W1e)
{
    __shared__ float4 sEA4[ETILE][4];       // plain eattr, 16KB
    __shared__ int sSrc[ETILE], sDst[ETILE];
    const int t    = threadIdx.x;
    const int lane = t & 31;
    const int warp = t >> 5;
    const int e0   = blockIdx.x * ETILE;

    sSrc[t] = srcIdx[e0 + t];
    sDst[t] = dstIdx[e0 + t];

    {
        const float4* ea4 = reinterpret_cast<const float4*>(
            eattr + (size_t)e0 * EDGE_DIM);
        float4* s4 = &sEA4[0][0];
        #pragma unroll
        for (int r = 0; r < 4; r++)
            s4[t + r * 256] = ea4[t + r * 256];
    }

    u64 wlo[16], whi[16];
    #pragma unroll
    for (int k = 0; k < 16; k++) {
        float4 wv = *reinterpret_cast<const float4*>(
            W1e + (size_t)k * HID + lane * 4);
        wlo[k] = pk2(wv.x, wv.y);
        whi[k] = pk2(wv.z, wv.w);
    }
    __syncthreads();

    const int ebase = warp * 32;

    float4 p_cur[4];
    #pragma unroll
    for (int q = 0; q < 4; q++)
        p_cur[q] = *reinterpret_cast<const float4*>(
            g_P + (size_t)sSrc[ebase + q] * HID + lane * 4);

    #pragma unroll
    for (int grp = 0; grp < 8; grp++) {
        float4 p_nxt[4];
        if (grp < 7) {
            #pragma unroll
            for (int q = 0; q < 4; q++)
                p_nxt[q] = *reinterpret_cast<const float4*>(
                    g_P + (size_t)sSrc[ebase + (grp + 1) * 4 + q] * HID + lane * 4);
        }
        #pragma unroll
        for (int q = 0; q < 4; q++) {
            const int e = ebase + grp * 4 + q;
            float4 q0 = sEA4[e][0], q1 = sEA4[e][1];
            float4 q2 = sEA4[e][2], q3 = sEA4[e][3];
            float ka[16] = {q0.x,q0.y,q0.z,q0.w, q1.x,q1.y,q1.z,q1.w,
                            q2.x,q2.y,q2.z,q2.w, q3.x,q3.y,q3.z,q3.w};
            u64 ac0 = pk2(p_cur[q].x, p_cur[q].y);
            u64 ac1 = pk2(p_cur[q].z, p_cur[q].w);
            #pragma unroll
            for (int k = 0; k < 16; k++) {
                u64 av = pk2(ka[k], ka[k]);
                fma2(ac0, av, wlo[k]);
                fma2(ac1, av, whi[k]);
            }
            float r0, r1, r2, r3;
            upk2(r0, r1, ac0); upk2(r2, r3, ac1);
            r0 = fmaxf(r0, 0.f); r1 = fmaxf(r1, 0.f);
            r2 = fmaxf(r2, 0.f); r3 = fmaxf(r3, 0.f);
            float* rp = g_R + (size_t)sDst[e] * HID + lane * 4;
            asm volatile("red.global.add.v4.f32 [%0], {%1,%2,%3,%4};"
                         :: "l"(rp), "f"(r0), "f"(r1), "f"(r2), "f"(r3)
                         : "memory");
        }
        #pragma unroll
        for (int q = 0; q < 4; q++) p_cur[q] = p_nxt[q];
    }
}

// ====== fused update (FFMA2 + double-buffered SMEM, 2 CTAs/SM) ======
#define UROWS     64
#define U_OFF_A2  0
#define U_OFF_B2  18432
#define U_OFF_SH  34816
#define U_OFF_DEG 68608
#define U_SMEM    68864
#define A2IDX(buf,r,k)  ((buf)*1152 + (r)*18 + (k))
#define B2IDX(buf,k,c2) ((buf)*1024 + (k)*64 + (c2))

__global__ void __launch_bounds__(256, 2) update_kernel(
    int ping, int layer,
    const float* __restrict__ Wtop,
    const float* __restrict__ B,
    const float* __restrict__ LG,
    const float* __restrict__ LB,
    const float* __restrict__ W1n,
    const float* __restrict__ B1n,
    const int*   __restrict__ batch,
    int hasNext)
{
    extern __shared__ char usm[];
    u64*   sA2  = (u64*)(usm + U_OFF_A2);
    u64*   sB2  = (u64*)(usm + U_OFF_B2);
    float* sH   = (float*)(usm + U_OFF_SH);
    float* sDeg = (float*)(usm + U_OFF_DEG);

    const float* __restrict__ h     = g_h[ping];
    float*       __restrict__ hout  = g_h[ping ^ 1];
    const float* __restrict__ wcomp = g_wcomp[layer];
    const int t  = threadIdx.x;
    const int n0 = blockIdx.x * UROWS;
    const int tx = t & 15;
    const int ty = t >> 4;
    const int col = tx * 8;

    const int aR = t >> 2, aC = (t & 3) * 4;
    int aN = n0 + aR; if (aN >= N_NODES) aN = 0;
    const int s0 = t * 2, s1 = t * 2 + 1;
    const int kr0 = s0 >> 5, cf0 = (s0 & 31) * 4;
    const int kr1 = s1 >> 5, cf1 = (s1 & 31) * 4;

    if (t < UROWS) {
        int n = n0 + t;
        sDeg[t] = (n < N_NODES) ? g_deg[n] : 0.f;
    }

    u64 acc2[4][4];
    {
        float4 b0 = *reinterpret_cast<const float4*>(B + col);
        float4 b1 = *reinterpret_cast<const float4*>(B + col + 4);
        u64 bb[4] = {pk2(b0.x,b0.y), pk2(b0.z,b0.w), pk2(b1.x,b1.y), pk2(b1.z,b1.w)};
        #pragma unroll
        for (int i = 0; i < 4; i++)
            #pragma unroll
            for (int j = 0; j < 4; j++) acc2[i][j] = bb[j];
    }

    {
        float4 vA = *reinterpret_cast<const float4*>(h + (size_t)aN * HID + aC);
        *reinterpret_cast<ulonglong2*>(&sA2[A2IDX(0, aR, aC)]) =
            make_ulonglong2(pk2(vA.x,vA.x), pk2(vA.y,vA.y));
        *reinterpret_cast<ulonglong2*>(&sA2[A2IDX(0, aR, aC + 2)]) =
            make_ulonglong2(pk2(vA.z,vA.z), pk2(vA.w,vA.w));
        float4 v0 = *reinterpret_cast<const float4*>(Wtop + (size_t)kr0 * HID + cf0);
        float4 v1 = *reinterpret_cast<const float4*>(Wtop + (size_t)kr1 * HID + cf1);
        *reinterpret_cast<ulonglong2*>(&sB2[B2IDX(0, kr0, cf0 >> 1)]) =
            *reinterpret_cast<ulonglong2*>(&v0);
        *reinterpret_cast<ulonglong2*>(&sB2[B2IDX(0, kr1, cf1 >> 1)]) =
            *reinterpret_cast<ulonglong2*>(&v1);
    }
    __syncthreads();

    for (int kt = 0; kt < 16; kt++) {
        const int cur = kt & 1, nxt = cur ^ 1;
        float4 rA, rB0, rB1;
        if (kt < 15) {
            const int k0 = (kt + 1) * 16;
            const float* ap = (k0 < 128)
                ? (h   + (size_t)aN * HID + k0 + aC)
                : (g_R + (size_t)aN * HID + (k0 - 128) + aC);
            rA = *reinterpret_cast<const float4*>(ap);
            const float* w0 = (k0 < 128)
                ? (Wtop  + (size_t)(k0 + kr0) * HID + cf0)
                : (wcomp + (size_t)(k0 - 128 + kr0) * HID + cf0);
            const float* w1 = (k0 < 128)
                ? (Wtop  + (size_t)(k0 + kr1) * HID + cf1)
                : (wcomp + (size_t)(k0 - 128 + kr1) * HID + cf1);
            rB0 = *reinterpret_cast<const float4*>(w0);
            rB1 = *reinterpret_cast<const float4*>(w1);
        }
        #pragma unroll
        for (int k = 0; k < 16; k++) {
            u64 a[4];
            #pragma unroll
            for (int i = 0; i < 4; i++)
                a[i] = sA2[A2IDX(cur, ty*4 + i, k)];
            ulonglong2 bA = *reinterpret_cast<ulonglong2*>(&sB2[B2IDX(cur, k, tx*4)]);
            ulonglong2 bB = *reinterpret_cast<ulonglong2*>(&sB2[B2IDX(cur, k, tx*4 + 2)]);
            #pragma unroll
            for (int i = 0; i < 4; i++) {
                fma2(acc2[i][0], a[i], bA.x);
                fma2(acc2[i][1], a[i], bA.y);
                fma2(acc2[i][2], a[i], bB.x);
                fma2(acc2[i][3], a[i], bB.y);
            }
        }
        if (kt < 15) {
            *reinterpret_cast<ulonglong2*>(&sA2[A2IDX(nxt, aR, aC)]) =
                make_ulonglong2(pk2(rA.x,rA.x), pk2(rA.y,rA.y));
            *reinterpret_cast<ulonglong2*>(&sA2[A2IDX(nxt, aR, aC + 2)]) =
                make_ulonglong2(pk2(rA.z,rA.z), pk2(rA.w,rA.w));
            *reinterpret_cast<ulonglong2*>(&sB2[B2IDX(nxt, kr0, cf0 >> 1)]) =
                *reinterpret_cast<ulonglong2*>(&rB0);
            *reinterpret_cast<ulonglong2*>(&sB2[B2IDX(nxt, kr1, cf1 >> 1)]) =
                *reinterpret_cast<ulonglong2*>(&rB1);
        }
        __syncthreads();
    }

    float4 g0  = *reinterpret_cast<const float4*>(LG + col);
    float4 g1  = *reinterpret_cast<const float4*>(LG + col + 4);
    float4 lb0 = *reinterpret_cast<const float4*>(LB + col);
    float4 lb1 = *reinterpret_cast<const float4*>(LB + col + 4);
    float4 bv0 = *reinterpret_cast<const float4*>(g_bvec[layer] + col);
    float4 bv1 = *reinterpret_cast<const float4*>(g_bvec[layer] + col + 4);
    float gg[8]  = {g0.x,g0.y,g0.z,g0.w,g1.x,g1.y,g1.z,g1.w};
    float lbv[8] = {lb0.x,lb0.y,lb0.z,lb0.w,lb1.x,lb1.y,lb1.z,lb1.w};
    float bvv[8] = {bv0.x,bv0.y,bv0.z,bv0.w,bv1.x,bv1.y,bv1.z,bv1.w};

    #pragma unroll
    for (int i = 0; i < 4; i++) {
        float acc[8];
        upk2(acc[0],acc[1],acc2[i][0]); upk2(acc[2],acc[3],acc2[i][1]);
        upk2(acc[4],acc[5],acc2[i][2]); upk2(acc[6],acc[7],acc2[i][3]);
        float dg = sDeg[ty * 4 + i];
        float s = 0.f, q = 0.f;
        #pragma unroll
        for (int j = 0; j < 8; j++) {
            acc[j] = fmaxf(acc[j] + dg * bvv[j], 0.f);
            s += acc[j]; q += acc[j] * acc[j];
        }
        #pragma unroll
        for (int m = 1; m < 16; m <<= 1) {
            s += __shfl_xor_sync(0xffffffffu, s, m);
            q += __shfl_xor_sync(0xffffffffu, q, m);
        }
        float mu  = s * (1.f / 128.f);
        float var = q * (1.f / 128.f) - mu * mu;
        float rs  = rsqrtf(var + 1e-5f);

        int n = n0 + ty * 4 + i;
        if (n < N_NODES) {
            const float* rp = h + (size_t)n * HID + col;
            float4 r0 = *reinterpret_cast<const float4*>(rp);
            float4 r1 = *reinterpret_cast<const float4*>(rp + 4);
            float rr[8] = {r0.x,r0.y,r0.z,r0.w,r1.x,r1.y,r1.z,r1.w};
            float o[8];
            #pragma unroll
            for (int j = 0; j < 8; j++) {
                float v = (acc[j] - mu) * rs * gg[j] + lbv[j];
                o[j] = fmaxf(v, 0.f) + rr[j];
            }
            if (hasNext) {
                float* sp = sH + (ty*4 + i) * 132 + col;
                *reinterpret_cast<float4*>(sp)     = make_float4(o[0],o[1],o[2],o[3]);
                *reinterpret_cast<float4*>(sp + 4) = make_float4(o[4],o[5],o[6],o[7]);
                float* op = hout + (size_t)n * HID + col;
                *reinterpret_cast<float4*>(op)     = make_float4(o[0],o[1],o[2],o[3]);
                *reinterpret_cast<float4*>(op + 4) = make_float4(o[4],o[5],o[6],o[7]);
            } else {
                int gph = batch[n];
                #pragma unroll
                for (int j = 0; j < 8; j++) {
                    atomicAdd(&g_mean[gph * HID + col + j], o[j]);
                    atomicMax(&g_maxe[gph * HID + col + j], fenc(o[j]));
                }
            }
        }
    }

    {
        float4 z = make_float4(0.f, 0.f, 0.f, 0.f);
        #pragma unroll
        for (int qq = 0; qq < 8; qq++) {
            int idx = qq * 256 + t;
            int n = n0 + (idx >> 5);
            if (n < N_NODES)
                reinterpret_cast<float4*>(g_R + (size_t)n * HID)[idx & 31] = z;
        }
    }

    if (!hasNext) return;

    {
        float4 b0 = *reinterpret_cast<const float4*>(B1n + col);
        float4 b1 = *reinterpret_cast<const float4*>(B1n + col + 4);
        u64 bb[4] = {pk2(b0.x,b0.y), pk2(b0.z,b0.w), pk2(b1.x,b1.y), pk2(b1.z,b1.w)};
        #pragma unroll
        for (int i = 0; i < 4; i++)
            #pragma unroll
            for (int j = 0; j < 4; j++) acc2[i][j] = bb[j];
    }
    {
        float4 v0 = *reinterpret_cast<const float4*>(W1n + (size_t)kr0 * HID + cf0);
        float4 v1 = *reinterpret_cast<const float4*>(W1n + (size_t)kr1 * HID + cf1);
        *reinterpret_cast<ulonglong2*>(&sB2[B2IDX(0, kr0, cf0 >> 1)]) =
            *reinterpret_cast<ulonglong2*>(&v0);
        *reinterpret_cast<ulonglong2*>(&sB2[B2IDX(0, kr1, cf1 >> 1)]) =
            *reinterpret_cast<ulonglong2*>(&v1);
    }
    __syncthreads();
    for (int kt = 0; kt < 8; kt++) {
        const int cur = kt & 1, nxt = cur ^ 1;
        float4 rB0, rB1;
        if (kt < 7) {
            const int k0 = (kt + 1) * 16;
            rB0 = *reinterpret_cast<const float4*>(W1n + (size_t)(k0 + kr0) * HID + cf0);
            rB1 = *reinterpret_cast<const float4*>(W1n + (size_t)(k0 + kr1) * HID + cf1);
        }
        #pragma unroll
        for (int k = 0; k < 16; k++) {
            u64 a[4];
            #pragma unroll
            for (int i = 0; i < 4; i++) {
                float av = sH[(ty*4 + i) * 132 + kt*16 + k];
                a[i] = pk2(av, av);
            }
            ulonglong2 bA = *reinterpret_cast<ulonglong2*>(&sB2[B2IDX(cur, k, tx*4)]);
            ulonglong2 bB = *reinterpret_cast<ulonglong2*>(&sB2[B2IDX(cur, k, tx*4 + 2)]);
            #pragma unroll
            for (int i = 0; i < 4; i++) {
                fma2(acc2[i][0], a[i], bA.x);
                fma2(acc2[i][1], a[i], bA.y);
                fma2(acc2[i][2], a[i], bB.x);
                fma2(acc2[i][3], a[i], bB.y);
            }
        }
        if (kt < 7) {
            *reinterpret_cast<ulonglong2*>(&sB2[B2IDX(nxt, kr0, cf0 >> 1)]) =
                *reinterpret_cast<ulonglong2*>(&rB0);
            *reinterpret_cast<ulonglong2*>(&sB2[B2IDX(nxt, kr1, cf1 >> 1)]) =
                *reinterpret_cast<ulonglong2*>(&rB1);
        }
        __syncthreads();
    }
    #pragma unroll
    for (int i = 0; i < 4; i++) {
        int n = n0 + ty * 4 + i;
        if (n < N_NODES) {
            float o[8];
            upk2(o[0],o[1],acc2[i][0]); upk2(o[2],o[3],acc2[i][1]);
            upk2(o[4],o[5],acc2[i][2]); upk2(o[6],o[7],acc2[i][3]);
            float* op = g_P + (size_t)n * HID + col;
            *reinterpret_cast<float4*>(op)     = make_float4(o[0],o[1],o[2],o[3]);
            *reinterpret_cast<float4*>(op + 4) = make_float4(o[4],o[5],o[6],o[7]);
        }
    }
}

// ================= readout =================
__global__ void readout_kernel(const float* __restrict__ W1,
                               const float* __restrict__ B1,
                               const float* __restrict__ W2,
                               const float* __restrict__ B2,
                               float* __restrict__ out)
{
    __shared__ float gv[256];
    __shared__ float red[128];
    const int g = blockIdx.x, t = threadIdx.x;
    float cnt = fmaxf(g_cnt[g], 1.f);
    gv[t]       = g_mean[g * HID + t] / cnt;
    gv[128 + t] = fdec(g_maxe[g * HID + t]);
    __syncthreads();
    float a = B1[t];
    #pragma unroll 8
    for (int k = 0; k < 256; k++)
        a = fmaf(gv[k], W1[(size_t)k * HID + t], a);
    a = fmaxf(a, 0.f) * W2[t];
    red[t] = a;
    __syncthreads();
    for (int s2 = 64; s2 > 0; s2 >>= 1) {
        if (t < s2) red[t] += red[t + s2];
        __syncthreads();
    }
    if (t == 0) out[g] = red[0] + B2[0];
}

// ================= launch =================
extern "C" void kernel_launch(void* const* d_in, const int* in_sizes, int n_in,
                              void* d_out, int out_size)
{
    const float* x     = (const float*)d_in[0];
    const int*   ei    = (const int*)  d_in[1];
    const float* eattr = (const float*)d_in[2];
    const int*   batch = (const int*)  d_in[3];
    const float* npw   = (const float*)d_in[4];
    const float* npb   = (const float*)d_in[5];
    const float* mw1   = (const float*)d_in[6];
    const float* mb1   = (const float*)d_in[7];
    const float* mw2   = (const float*)d_in[8];
    const float* mb2   = (const float*)d_in[9];
    const float* uw    = (const float*)d_in[10];
    const float* ub    = (const float*)d_in[11];
    const float* lg    = (const float*)d_in[12];
    const float* lb    = (const float*)d_in[13];
    const float* fw1   = (const float*)d_in[14];
    const float* fb1   = (const float*)d_in[15];
    const float* fw2   = (const float*)d_in[16];
    const float* fb2   = (const float*)d_in[17];
    float* out = (float*)d_out;

    const int* srcIdx = ei;
    const int* dstIdx = ei + N_EDGES;

    cudaFuncSetAttribute(update_kernel,
                         cudaFuncAttributeMaxDynamicSharedMemorySize, U_SMEM);
    cudaFuncSetAttribute(proj_pre_kernel,
                         cudaFuncAttributeMaxDynamicSharedMemorySize, PP_SMEM);

    init_kernel<<<(N_NODES * HID / 4) / 256, 256>>>();
    setup_kernel<<<SETUP_BLKS, 256>>>(dstIdx, batch, mw2, uw, mb2);
    proj_pre_kernel<<<(N_NODES + 63) / 64, 256, PP_SMEM>>>(x, npw, npb, mw1, mb1);

    int ping = 0;
    for (int l = 0; l < NLAYERS; l++) {
        const float* W1l  = mw1 + (size_t)l * (HID + EDGE_DIM) * HID;
        const float* W1el = W1l + (size_t)HID * HID;
        const float* Wul  = uw  + (size_t)l * 2 * HID * HID;
        const int hasNext = (l + 1 < NLAYERS);
        const float* W1n  = hasNext ? (W1l + (size_t)(HID + EDGE_DIM) * HID) : W1l;
        const float* B1n  = hasNext ? (mb1 + (size_t)(l + 1) * HID) : mb1;

        edge_kernel<<<N_ETILES, 256>>>(eattr, srcIdx, dstIdx, W1el);
        update_kernel<<<(N_NODES + UROWS - 1) / UROWS, 256, U_SMEM>>>(
            ping, l, Wul, ub + (size_t)l * HID,
            lg + (size_t)l * HID, lb + (size_t)l * HID,
            W1n, B1n, batch, hasNext);
        ping ^= 1;
    }

    readout_kernel<<<NGRAPHS, 128>>>(fw1, fb1, fw2, fb2, out);
}

// round 15
// speedup vs baseline: 1.4498x; 1.0691x over previous
#include <cuda_runtime.h>
#include <cuda_bf16.h>
#include <cstdint>
#include <math.h>

#define N_NODES   20000
#define N_EDGES   640000
#define IN_CH     64
#define EDGE_DIM  16
#define HID       128
#define NLAYERS   3
#define NGRAPHS   128
#define ETILE     256
#define N_ETILES  (N_EDGES / ETILE)   // 2500

typedef unsigned long long u64;

// ================= scratch (device globals) =================
__device__ float     g_h[2][N_NODES * HID];
__device__ float     g_P[N_NODES * HID];
__device__ float     g_R[N_NODES * HID];
__device__ float     g_wcomp[NLAYERS][HID * HID];
__device__ float     g_bvec[NLAYERS][HID];
__device__ float     g_deg[N_NODES];
__device__ float     g_mean[NGRAPHS * HID];
__device__ unsigned  g_maxe[NGRAPHS * HID];
__device__ float     g_cnt[NGRAPHS];

__device__ __forceinline__ unsigned fenc(float f) {
    unsigned u = __float_as_uint(f);
    return (u & 0x80000000u) ? ~u : (u | 0x80000000u);
}
__device__ __forceinline__ float fdec(unsigned u) {
    return (u & 0x80000000u) ? __uint_as_float(u & 0x7FFFFFFFu)
                             : __uint_as_float(~u);
}
#define ENC_NEG_INF 0x007FFFFFu

// ---- packed f32x2 helpers ----
__device__ __forceinline__ u64 pk2(float lo, float hi) {
    u64 r; asm("mov.b64 %0, {%1, %2};" : "=l"(r) : "f"(lo), "f"(hi)); return r;
}
__device__ __forceinline__ void upk2(float& lo, float& hi, u64 v) {
    asm("mov.b64 {%0, %1}, %2;" : "=f"(lo), "=f"(hi) : "l"(v));
}
__device__ __forceinline__ void fma2(u64& d, u64 a, u64 b) {
    asm("fma.rn.f32x2 %0, %1, %2, %0;" : "+l"(d) : "l"(a), "l"(b));
}

// ---- cp.async helpers ----
__device__ __forceinline__ uint32_t smem_u32(const void* p) {
    uint32_t a;
    asm("{ .reg .u64 tmp; cvta.to.shared.u64 tmp, %1; cvt.u32.u64 %0, tmp; }"
        : "=r"(a) : "l"(p));
    return a;
}
#define CP_ASYNC16(dst, src) \
    asm volatile("cp.async.ca.shared.global [%0], [%1], 16;" \
                 :: "r"(dst), "l"(src) : "memory")
#define CP_COMMIT() asm volatile("cp.async.commit_group;" ::: "memory")
#define CP_WAIT(n)  asm volatile("cp.async.wait_group %0;" :: "n"(n) : "memory")

// ======= init: zero deg, pool accum, cnt, R (one kernel) =======
__global__ void init_kernel() {
    int i = blockIdx.x * 256 + threadIdx.x;   // grid 2500
    reinterpret_cast<float4*>(g_R)[i] = make_float4(0.f, 0.f, 0.f, 0.f);
    if (i < N_NODES) g_deg[i] = 0.f;
    if (i < NGRAPHS * HID) { g_mean[i] = 0.f; g_maxe[i] = ENC_NEG_INF; }
    if (i < NGRAPHS) g_cnt[i] = 0.f;
}

// ======= setup: deg count | cnt count | tiled compose (block ranges) ======
#define SETUP_DEG_BLKS  (N_EDGES / 256)                 // 2500
#define SETUP_CNT_BLKS  ((N_NODES + 255) / 256)         // 79
#define SETUP_CMP_BLKS  (NLAYERS * 4)                   // 12
#define SETUP_BLKS      (SETUP_DEG_BLKS + SETUP_CNT_BLKS + SETUP_CMP_BLKS)

__global__ void __launch_bounds__(256) setup_kernel(
    const int*   __restrict__ dstIdx,
    const int*   __restrict__ batch,
    const float* __restrict__ mw2,
    const float* __restrict__ uw,
    const float* __restrict__ mb2)
{
    const int blk = blockIdx.x;
    const int t   = threadIdx.x;

    if (blk < SETUP_DEG_BLKS) {
        int e = blk * 256 + t;
        atomicAdd(&g_deg[dstIdx[e]], 1.f);
        return;
    }
    if (blk < SETUP_DEG_BLKS + SETUP_CNT_BLKS) {
        int i = (blk - SETUP_DEG_BLKS) * 256 + t;
        if (i >= N_NODES) return;
        int g = batch[i];
        unsigned m = __match_any_sync(__activemask(), g);
        int leader = __ffs(m) - 1;
        if ((t & 31) == leader)
            atomicAdd(&g_cnt[g], (float)__popc(m));
        return;
    }

    const int cb   = blk - SETUP_DEG_BLKS - SETUP_CNT_BLKS;
    const int l    = cb >> 2;
    const int j0   = (cb & 3) * 32;
    const float* W2    = mw2 + (size_t)l * HID * HID;
    const float* WuBot = uw  + (size_t)l * 2 * HID * HID + (size_t)HID * HID;
    const float* b2    = mb2 + (size_t)l * HID;

    __shared__ float sA[32][17];
    __shared__ float sB[16][128];
    const int tx = t & 15;
    const int ty = t >> 4;
    const int col = tx * 8;

    float acc[2][8];
    #pragma unroll
    for (int i = 0; i < 2; i++)
        #pragma unroll
        for (int j = 0; j < 8; j++) acc[i][j] = 0.f;

    for (int kt = 0; kt < 8; kt++) {
        const int k0 = kt * 16;
        __syncthreads();
        #pragma unroll
        for (int q = 0; q < 2; q++) {
            int s = t * 2 + q;
            int r = s >> 4, c = s & 15;
            sA[r][c] = W2[(size_t)(j0 + r) * HID + k0 + c];
        }
        #pragma unroll
        for (int q = 0; q < 2; q++) {
            int s  = t * 2 + q;
            int kr = s >> 5;
            int c  = (s & 31) * 4;
            *reinterpret_cast<float4*>(&sB[kr][c]) =
                *reinterpret_cast<const float4*>(
                    WuBot + (size_t)(k0 + kr) * HID + c);
        }
        __syncthreads();
        #pragma unroll
        for (int k = 0; k < 16; k++) {
            float a0 = sA[ty*2][k], a1 = sA[ty*2 + 1][k];
            float4 b0 = *reinterpret_cast<float4*>(&sB[k][col]);
            float4 b1 = *reinterpret_cast<float4*>(&sB[k][col + 4]);
            float bb[8] = {b0.x,b0.y,b0.z,b0.w,b1.x,b1.y,b1.z,b1.w};
            #pragma unroll
            for (int j = 0; j < 8; j++) {
                acc[0][j] = fmaf(a0, bb[j], acc[0][j]);
                acc[1][j] = fmaf(a1, bb[j], acc[1][j]);
            }
        }
    }
    #pragma unroll
    for (int i = 0; i < 2; i++) {
        float* op = g_wcomp[l] + (size_t)(j0 + ty*2 + i) * HID + col;
        *reinterpret_cast<float4*>(op)     = make_float4(acc[i][0],acc[i][1],acc[i][2],acc[i][3]);
        *reinterpret_cast<float4*>(op + 4) = make_float4(acc[i][4],acc[i][5],acc[i][6],acc[i][7]);
    }
    if ((cb & 3) == 0 && t < HID) {
        float bv = 0.f;
        #pragma unroll 8
        for (int c = 0; c < HID; c++)
            bv = fmaf(b2[c], WuBot[(size_t)c * HID + t], bv);
        g_bvec[l][t] = bv;
    }
}

// ========== fused proj+pre: h0 = x@Wnp + bnp ; P = h0@W1 + b1 ==========
#define PP_OFF_SX 0                       // 64*68*4  = 17408
#define PP_OFF_SB 17408                   // u64 16*64*8 = 8192
#define PP_OFF_SH 25600                   // 64*132*4 = 33792
#define PP_SMEM   59392

__global__ void __launch_bounds__(256, 2) proj_pre_kernel(
    const float* __restrict__ x,
    const float* __restrict__ Wnp, const float* __restrict__ Bnp,
    const float* __restrict__ W1,  const float* __restrict__ B1)
{
    extern __shared__ char psm[];
    float (*sX)[68] = (float(*)[68])(psm + PP_OFF_SX);
    u64*   sB2      = (u64*)(psm + PP_OFF_SB);
    float* sH       = (float*)(psm + PP_OFF_SH);

    const int t  = threadIdx.x;
    const int n0 = blockIdx.x * 64;
    const int tx = t & 15;
    const int ty = t >> 4;
    const int col = tx * 8;

    #pragma unroll
    for (int r4 = 0; r4 < 4; r4++) {
        int idx = t + r4 * 256;
        int row = idx >> 4, c4 = (idx & 15) * 4;
        int n = n0 + row; if (n >= N_NODES) n = 0;
        float4 v = *reinterpret_cast<const float4*>(x + (size_t)n * IN_CH + c4);
        *reinterpret_cast<float4*>(&sX[row][c4]) = v;
    }

    u64 acc2[4][4];
    {
        float4 b0 = *reinterpret_cast<const float4*>(Bnp + col);
        float4 b1 = *reinterpret_cast<const float4*>(Bnp + col + 4);
        u64 bb[4] = {pk2(b0.x,b0.y), pk2(b0.z,b0.w), pk2(b1.x,b1.y), pk2(b1.z,b1.w)};
        #pragma unroll
        for (int i = 0; i < 4; i++)
            #pragma unroll
            for (int j = 0; j < 4; j++) acc2[i][j] = bb[j];
    }

    for (int kt = 0; kt < 4; kt++) {
        __syncthreads();
        #pragma unroll
        for (int q = 0; q < 2; q++) {
            int s  = t * 2 + q;
            int kr = s >> 5;
            int cf = (s & 31) * 4;
            float4 v = *reinterpret_cast<const float4*>(
                Wnp + (size_t)(kt * 16 + kr) * HID + cf);
            *reinterpret_cast<ulonglong2*>(&sB2[kr * 64 + (cf >> 1)]) =
                *reinterpret_cast<ulonglong2*>(&v);
        }
        __syncthreads();
        #pragma unroll
        for (int k = 0; k < 16; k++) {
            u64 a[4];
            #pragma unroll
            for (int i = 0; i < 4; i++) {
                float av = sX[ty*4 + i][kt*16 + k];
                a[i] = pk2(av, av);
            }
            ulonglong2 bA = *reinterpret_cast<ulonglong2*>(&sB2[k * 64 + tx*4]);
            ulonglong2 bB = *reinterpret_cast<ulonglong2*>(&sB2[k * 64 + tx*4 + 2]);
            #pragma unroll
            for (int i = 0; i < 4; i++) {
                fma2(acc2[i][0], a[i], bA.x);
                fma2(acc2[i][1], a[i], bA.y);
                fma2(acc2[i][2], a[i], bB.x);
                fma2(acc2[i][3], a[i], bB.y);
            }
        }
    }
    __syncthreads();

    #pragma unroll
    for (int i = 0; i < 4; i++) {
        float o[8];
        upk2(o[0],o[1],acc2[i][0]); upk2(o[2],o[3],acc2[i][1]);
        upk2(o[4],o[5],acc2[i][2]); upk2(o[6],o[7],acc2[i][3]);
        int n = n0 + ty*4 + i;
        float* sp = sH + (ty*4 + i) * 132 + col;
        *reinterpret_cast<float4*>(sp)     = make_float4(o[0],o[1],o[2],o[3]);
        *reinterpret_cast<float4*>(sp + 4) = make_float4(o[4],o[5],o[6],o[7]);
        if (n < N_NODES) {
            float* op = g_h[0] + (size_t)n * HID + col;
            *reinterpret_cast<float4*>(op)     = make_float4(o[0],o[1],o[2],o[3]);
            *reinterpret_cast<float4*>(op + 4) = make_float4(o[4],o[5],o[6],o[7]);
        }
    }

    {
        float4 b0 = *reinterpret_cast<const float4*>(B1 + col);
        float4 b1 = *reinterpret_cast<const float4*>(B1 + col + 4);
        u64 bb[4] = {pk2(b0.x,b0.y), pk2(b0.z,b0.w), pk2(b1.x,b1.y), pk2(b1.z,b1.w)};
        #pragma unroll
        for (int i = 0; i < 4; i++)
            #pragma unroll
            for (int j = 0; j < 4; j++) acc2[i][j] = bb[j];
    }
    for (int kt = 0; kt < 8; kt++) {
        __syncthreads();
        #pragma unroll
        for (int q = 0; q < 2; q++) {
            int s  = t * 2 + q;
            int kr = s >> 5;
            int cf = (s & 31) * 4;
            float4 v = *reinterpret_cast<const float4*>(
                W1 + (size_t)(kt * 16 + kr) * HID + cf);
            *reinterpret_cast<ulonglong2*>(&sB2[kr * 64 + (cf >> 1)]) =
                *reinterpret_cast<ulonglong2*>(&v);
        }
        __syncthreads();
        #pragma unroll
        for (int k = 0; k < 16; k++) {
            u64 a[4];
            #pragma unroll
            for (int i = 0; i < 4; i++) {
                float av = sH[(ty*4 + i) * 132 + kt*16 + k];
                a[i] = pk2(av, av);
            }
            ulonglong2 bA = *reinterpret_cast<ulonglong2*>(&sB2[k * 64 + tx*4]);
            ulonglong2 bB = *reinterpret_cast<ulonglong2*>(&sB2[k * 64 + tx*4 + 2]);
            #pragma unroll
            for (int i = 0; i < 4; i++) {
                fma2(acc2[i][0], a[i], bA.x);
                fma2(acc2[i][1], a[i], bA.y);
                fma2(acc2[i][2], a[i], bB.x);
                fma2(acc2[i][3], a[i], bB.y);
            }
        }
    }
    #pragma unroll
    for (int i = 0; i < 4; i++) {
        int n = n0 + ty*4 + i;
        if (n < N_NODES) {
            float o[8];
            upk2(o[0],o[1],acc2[i][0]); upk2(o[2],o[3],acc2[i][1]);
            upk2(o[4],o[5],acc2[i][2]); upk2(o[6],o[7],acc2[i][3]);
            float* op = g_P + (size_t)n * HID + col;
            *reinterpret_cast<float4*>(op)     = make_float4(o[0],o[1],o[2],o[3]);
            *reinterpret_cast<float4*>(op + 4) = make_float4(o[4],o[5],o[6],o[7]);
        }
    }
}

// ================= edge kernel: round-12 best (unchanged) ====
__global__ void __launch_bounds__(256) edge_kernel(
    const float* __restrict__ eattr,
    const int*   __restrict__ srcIdx,
    const int*   __restrict__ dstIdx,
    const float* __restrict__ W1e)
{
    __shared__ float4 sEA4[ETILE][4];
    __shared__ int sSrc[ETILE], sDst[ETILE];
    const int t    = threadIdx.x;
    const int lane = t & 31;
    const int warp = t >> 5;
    const int e0   = blockIdx.x * ETILE;

    sSrc[t] = srcIdx[e0 + t];
    sDst[t] = dstIdx[e0 + t];

    {
        const float4* ea4 = reinterpret_cast<const float4*>(
            eattr + (size_t)e0 * EDGE_DIM);
        float4* s4 = &sEA4[0][0];
        #pragma unroll
        for (int r = 0; r < 4; r++)
            s4[t + r * 256] = ea4[t + r * 256];
    }

    u64 wlo[16], whi[16];
    #pragma unroll
    for (int k = 0; k < 16; k++) {
        float4 wv = *reinterpret_cast<const float4*>(
            W1e + (size_t)k * HID + lane * 4);
        wlo[k] = pk2(wv.x, wv.y);
        whi[k] = pk2(wv.z, wv.w);
    }
    __syncthreads();

    const int ebase = warp * 32;

    float4 p_cur[4];
    #pragma unroll
    for (int q = 0; q < 4; q++)
        p_cur[q] = *reinterpret_cast<const float4*>(
            g_P + (size_t)sSrc[ebase + q] * HID + lane * 4);

    #pragma unroll
    for (int grp = 0; grp < 8; grp++) {
        float4 p_nxt[4];
        if (grp < 7) {
            #pragma unroll
            for (int q = 0; q < 4; q++)
                p_nxt[q] = *reinterpret_cast<const float4*>(
                    g_P + (size_t)sSrc[ebase + (grp + 1) * 4 + q] * HID + lane * 4);
        }
        #pragma unroll
        for (int q = 0; q < 4; q++) {
            const int e = ebase + grp * 4 + q;
            float4 q0 = sEA4[e][0], q1 = sEA4[e][1];
            float4 q2 = sEA4[e][2], q3 = sEA4[e][3];
            float ka[16] = {q0.x,q0.y,q0.z,q0.w, q1.x,q1.y,q1.z,q1.w,
                            q2.x,q2.y,q2.z,q2.w, q3.x,q3.y,q3.z,q3.w};
            u64 ac0 = pk2(p_cur[q].x, p_cur[q].y);
            u64 ac1 = pk2(p_cur[q].z, p_cur[q].w);
            #pragma unroll
            for (int k = 0; k < 16; k++) {
                u64 av = pk2(ka[k], ka[k]);
                fma2(ac0, av, wlo[k]);
                fma2(ac1, av, whi[k]);
            }
            float r0, r1, r2, r3;
            upk2(r0, r1, ac0); upk2(r2, r3, ac1);
            r0 = fmaxf(r0, 0.f); r1 = fmaxf(r1, 0.f);
            r2 = fmaxf(r2, 0.f); r3 = fmaxf(r3, 0.f);
            float* rp = g_R + (size_t)sDst[e] * HID + lane * 4;
            asm volatile("red.global.add.v4.f32 [%0], {%1,%2,%3,%4};"
                         :: "l"(rp), "f"(r0), "f"(r1), "f"(r2), "f"(r3)
                         : "memory");
        }
        #pragma unroll
        for (int q = 0; q < 4; q++) p_cur[q] = p_nxt[q];
    }
}

// ====== fused update: cp.async 3-stage pipeline, plain-float staging ======
#define UROWS     64
#define STAGES    3
#define U_OFF_AF  0                         // 3*64*20*4  = 15360
#define U_OFF_BF  15360                     // 3*16*128*4 = 24576
#define U_OFF_SH  39936                     // 64*132*4   = 33792
#define U_OFF_DEG 73728                     // 256
#define U_SMEM    73984
#define AFIDX(st,r,k)  ((((st)*64 + (r))*20) + (k))
#define BFIDX(st,k,c)  ((((st)*16 + (k))*128) + (c))

__global__ void __launch_bounds__(256, 2) update_kernel(
    int ping, int layer,
    const float* __restrict__ Wtop,
    const float* __restrict__ B,
    const float* __restrict__ LG,
    const float* __restrict__ LB,
    const float* __restrict__ W1n,
    const float* __restrict__ B1n,
    const int*   __restrict__ batch,
    int hasNext)
{
    extern __shared__ char usm[];
    float* sAf  = (float*)(usm + U_OFF_AF);
    float* sBf  = (float*)(usm + U_OFF_BF);
    float* sH   = (float*)(usm + U_OFF_SH);
    float* sDeg = (float*)(usm + U_OFF_DEG);
    const uint32_t aBase = smem_u32(sAf);
    const uint32_t bBase = smem_u32(sBf);

    const float* __restrict__ h     = g_h[ping];
    float*       __restrict__ hout  = g_h[ping ^ 1];
    const float* __restrict__ wcomp = g_wcomp[layer];
    const int t  = threadIdx.x;
    const int n0 = blockIdx.x * UROWS;
    const int tx = t & 15;
    const int ty = t >> 4;
    const int col = tx * 8;

    const int aR = t >> 2, aC = (t & 3) * 4;
    int aN = n0 + aR; if (aN >= N_NODES) aN = 0;
    const int s0 = t * 2, s1 = t * 2 + 1;
    const int kr0 = s0 >> 5, cf0 = (s0 & 31) * 4;
    const int kr1 = s1 >> 5, cf1 = (s1 & 31) * 4;
    const uint32_t aDst0 = aBase + (uint32_t)(aR * 20 + aC) * 4u;
    const uint32_t bDst0 = bBase + (uint32_t)(kr0 * 128 + cf0) * 4u;
    const uint32_t bDst1 = bBase + (uint32_t)(kr1 * 128 + cf1) * 4u;
    const uint32_t aStg  = 64u * 20u * 4u;
    const uint32_t bStg  = 16u * 128u * 4u;

    if (t < UROWS) {
        int n = n0 + t;
        sDeg[t] = (n < N_NODES) ? g_deg[n] : 0.f;
    }

    u64 acc2[4][4];
    {
        float4 b0 = *reinterpret_cast<const float4*>(B + col);
        float4 b1 = *reinterpret_cast<const float4*>(B + col + 4);
        u64 bb[4] = {pk2(b0.x,b0.y), pk2(b0.z,b0.w), pk2(b1.x,b1.y), pk2(b1.z,b1.w)};
        #pragma unroll
        for (int i = 0; i < 4; i++)
            #pragma unroll
            for (int j = 0; j < 4; j++) acc2[i][j] = bb[j];
    }

    // ---- main GEMM: [h,R] @ [Wtop;wcomp], 16 k-tiles, cp.async 3-stage ----
    #define ISSUE_MAIN(kt_, st_) do {                                         \
        const int k0_ = (kt_) * 16;                                           \
        const float* ap_ = (k0_ < 128)                                        \
            ? (h   + (size_t)aN * HID + k0_ + aC)                             \
            : (g_R + (size_t)aN * HID + (k0_ - 128) + aC);                    \
        CP_ASYNC16(aDst0 + (st_) * aStg, ap_);                                \
        const float* w0_ = (k0_ < 128)                                        \
            ? (Wtop  + (size_t)(k0_ + kr0) * HID + cf0)                       \
            : (wcomp + (size_t)(k0_ - 128 + kr0) * HID + cf0);                \
        const float* w1_ = (k0_ < 128)                                        \
            ? (Wtop  + (size_t)(k0_ + kr1) * HID + cf1)                       \
            : (wcomp + (size_t)(k0_ - 128 + kr1) * HID + cf1);                \
        CP_ASYNC16(bDst0 + (st_) * bStg, w0_);                                \
        CP_ASYNC16(bDst1 + (st_) * bStg, w1_);                                \
    } while (0)

    ISSUE_MAIN(0, 0); CP_COMMIT();
    ISSUE_MAIN(1, 1); CP_COMMIT();

    for (int kt = 0; kt < 16; kt++) {
        const int cur = kt % STAGES;
        CP_WAIT(1);
        __syncthreads();
        if (kt + 2 < 16) { ISSUE_MAIN(kt + 2, (kt + 2) % STAGES); }
        CP_COMMIT();
        #pragma unroll
        for (int k = 0; k < 16; k++) {
            u64 a[4];
            #pragma unroll
            for (int i = 0; i < 4; i++) {
                float av = sAf[AFIDX(cur, ty*4 + i, k)];
                a[i] = pk2(av, av);
            }
            ulonglong2 bA = *reinterpret_cast<ulonglong2*>(&sBf[BFIDX(cur, k, tx*8)]);
            ulonglong2 bB = *reinterpret_cast<ulonglong2*>(&sBf[BFIDX(cur, k, tx*8 + 4)]);
            #pragma unroll
            for (int i = 0; i < 4; i++) {
                fma2(acc2[i][0], a[i], bA.x);
                fma2(acc2[i][1], a[i], bA.y);
                fma2(acc2[i][2], a[i], bB.x);
                fma2(acc2[i][3], a[i], bB.y);
            }
        }
    }
    CP_WAIT(0);
    #undef ISSUE_MAIN

    float4 g0  = *reinterpret_cast<const float4*>(LG + col);
    float4 g1  = *reinterpret_cast<const float4*>(LG + col + 4);
    float4 lb0 = *reinterpret_cast<const float4*>(LB + col);
    float4 lb1 = *reinterpret_cast<const float4*>(LB + col + 4);
    float4 bv0 = *reinterpret_cast<const float4*>(g_bvec[layer] + col);
    float4 bv1 = *reinterpret_cast<const float4*>(g_bvec[layer] + col + 4);
    float gg[8]  = {g0.x,g0.y,g0.z,g0.w,g1.x,g1.y,g1.z,g1.w};
    float lbv[8] = {lb0.x,lb0.y,lb0.z,lb0.w,lb1.x,lb1.y,lb1.z,lb1.w};
    float bvv[8] = {bv0.x,bv0.y,bv0.z,bv0.w,bv1.x,bv1.y,bv1.z,bv1.w};

    #pragma unroll
    for (int i = 0; i < 4; i++) {
        float acc[8];
        upk2(acc[0],acc[1],acc2[i][0]); upk2(acc[2],acc[3],acc2[i][1]);
        upk2(acc[4],acc[5],acc2[i][2]); upk2(acc[6],acc[7],acc2[i][3]);
        float dg = sDeg[ty * 4 + i];
        float s = 0.f, q = 0.f;
        #pragma unroll
        for (int j = 0; j < 8; j++) {
            acc[j] = fmaxf(acc[j] + dg * bvv[j], 0.f);
            s += acc[j]; q += acc[j] * acc[j];
        }
        #pragma unroll
        for (int m = 1; m < 16; m <<= 1) {
            s += __shfl_xor_sync(0xffffffffu, s, m);
            q += __shfl_xor_sync(0xffffffffu, q, m);
        }
        float mu  = s * (1.f / 128.f);
        float var = q * (1.f / 128.f) - mu * mu;
        float rs  = rsqrtf(var + 1e-5f);

        int n = n0 + ty * 4 + i;
        if (n < N_NODES) {
            const float* rp = h + (size_t)n * HID + col;
            float4 r0 = *reinterpret_cast<const float4*>(rp);
            float4 r1 = *reinterpret_cast<const float4*>(rp + 4);
            float rr[8] = {r0.x,r0.y,r0.z,r0.w,r1.x,r1.y,r1.z,r1.w};
            float o[8];
            #pragma unroll
            for (int j = 0; j < 8; j++) {
                float v = (acc[j] - mu) * rs * gg[j] + lbv[j];
                o[j] = fmaxf(v, 0.f) + rr[j];
            }
            if (hasNext) {
                float* sp = sH + (ty*4 + i) * 132 + col;
                *reinterpret_cast<float4*>(sp)     = make_float4(o[0],o[1],o[2],o[3]);
                *reinterpret_cast<float4*>(sp + 4) = make_float4(o[4],o[5],o[6],o[7]);
                float* op = hout + (size_t)n * HID + col;
                *reinterpret_cast<float4*>(op)     = make_float4(o[0],o[1],o[2],o[3]);
                *reinterpret_cast<float4*>(op + 4) = make_float4(o[4],o[5],o[6],o[7]);
            } else {
                int gph = batch[n];
                #pragma unroll
                for (int j = 0; j < 8; j++) {
                    atomicAdd(&g_mean[gph * HID + col + j], o[j]);
                    atomicMax(&g_maxe[gph * HID + col + j], fenc(o[j]));
                }
            }
        }
    }

    // zero own R rows for next layer
    {
        float4 z = make_float4(0.f, 0.f, 0.f, 0.f);
        #pragma unroll
        for (int qq = 0; qq < 8; qq++) {
            int idx = qq * 256 + t;
            int n = n0 + (idx >> 5);
            if (n < N_NODES)
                reinterpret_cast<float4*>(g_R + (size_t)n * HID)[idx & 31] = z;
        }
    }

    if (!hasNext) return;

    // ---- P = h' @ W1n + B1n (A from sH; W1n via cp.async, 3-stage) ----
    {
        float4 b0 = *reinterpret_cast<const float4*>(B1n + col);
        float4 b1 = *reinterpret_cast<const float4*>(B1n + col + 4);
        u64 bb[4] = {pk2(b0.x,b0.y), pk2(b0.z,b0.w), pk2(b1.x,b1.y), pk2(b1.z,b1.w)};
        #pragma unroll
        for (int i = 0; i < 4; i++)
            #pragma unroll
            for (int j = 0; j < 4; j++) acc2[i][j] = bb[j];
    }
    #define ISSUE_P(kt_, st_) do {                                            \
        const int k0_ = (kt_) * 16;                                           \
        CP_ASYNC16(bDst0 + (st_) * bStg,                                      \
                   W1n + (size_t)(k0_ + kr0) * HID + cf0);                    \
        CP_ASYNC16(bDst1 + (st_) * bStg,                                      \
                   W1n + (size_t)(k0_ + kr1) * HID + cf1);                    \
    } while (0)

    ISSUE_P(0, 0); CP_COMMIT();
    ISSUE_P(1, 1); CP_COMMIT();

    for (int kt = 0; kt < 8; kt++) {
        const int cur = kt % STAGES;
        CP_WAIT(1);
        __syncthreads();
        if (kt + 2 < 8) { ISSUE_P(kt + 2, (kt + 2) % STAGES); }
        CP_COMMIT();
        #pragma unroll
        for (int k = 0; k < 16; k++) {
            u64 a[4];
            #pragma unroll
            for (int i = 0; i < 4; i++) {
                float av = sH[(ty*4 + i) * 132 + kt*16 + k];
                a[i] = pk2(av, av);
            }
            ulonglong2 bA = *reinterpret_cast<ulonglong2*>(&sBf[BFIDX(cur, k, tx*8)]);
            ulonglong2 bB = *reinterpret_cast<ulonglong2*>(&sBf[BFIDX(cur, k, tx*8 + 4)]);
            #pragma unroll
            for (int i = 0; i < 4; i++) {
                fma2(acc2[i][0], a[i], bA.x);
                fma2(acc2[i][1], a[i], bA.y);
                fma2(acc2[i][2], a[i], bB.x);
                fma2(acc2[i][3], a[i], bB.y);
            }
        }
    }
    CP_WAIT(0);
    #undef ISSUE_P

    #pragma unroll
    for (int i = 0; i < 4; i++) {
        int n = n0 + ty * 4 + i;
        if (n < N_NODES) {
            float o[8];
            upk2(o[0],o[1],acc2[i][0]); upk2(o[2],o[3],acc2[i][1]);
            upk2(o[4],o[5],acc2[i][2]); upk2(o[6],o[7],acc2[i][3]);
            float* op = g_P + (size_t)n * HID + col;
            *reinterpret_cast<float4*>(op)     = make_float4(o[0],o[1],o[2],o[3]);
            *reinterpret_cast<float4*>(op + 4) = make_float4(o[4],o[5],o[6],o[7]);
        }
    }
}

// ================= readout =================
__global__ void readout_kernel(const float* __restrict__ W1,
                               const float* __restrict__ B1,
                               const float* __restrict__ W2,
                               const float* __restrict__ B2,
                               float* __restrict__ out)
{
    __shared__ float gv[256];
    __shared__ float red[128];
    const int g = blockIdx.x, t = threadIdx.x;
    float cnt = fmaxf(g_cnt[g], 1.f);
    gv[t]       = g_mean[g * HID + t] / cnt;
    gv[128 + t] = fdec(g_maxe[g * HID + t]);
    __syncthreads();
    float a = B1[t];
    #pragma unroll 8
    for (int k = 0; k < 256; k++)
        a = fmaf(gv[k], W1[(size_t)k * HID + t], a);
    a = fmaxf(a, 0.f) * W2[t];
    red[t] = a;
    __syncthreads();
    for (int s2 = 64; s2 > 0; s2 >>= 1) {
        if (t < s2) red[t] += red[t + s2];
        __syncthreads();
    }
    if (t == 0) out[g] = red[0] + B2[0];
}

// ================= launch =================
extern "C" void kernel_launch(void* const* d_in, const int* in_sizes, int n_in,
                              void* d_out, int out_size)
{
    const float* x     = (const float*)d_in[0];
    const int*   ei    = (const int*)  d_in[1];
    const float* eattr = (const float*)d_in[2];
    const int*   batch = (const int*)  d_in[3];
    const float* npw   = (const float*)d_in[4];
    const float* npb   = (const float*)d_in[5];
    const float* mw1   = (const float*)d_in[6];
    const float* mb1   = (const float*)d_in[7];
    const float* mw2   = (const float*)d_in[8];
    const float* mb2   = (const float*)d_in[9];
    const float* uw    = (const float*)d_in[10];
    const float* ub    = (const float*)d_in[11];
    const float* lg    = (const float*)d_in[12];
    const float* lb    = (const float*)d_in[13];
    const float* fw1   = (const float*)d_in[14];
    const float* fb1   = (const float*)d_in[15];
    const float* fw2   = (const float*)d_in[16];
    const float* fb2   = (const float*)d_in[17];
    float* out = (float*)d_out;

    const int* srcIdx = ei;
    const int* dstIdx = ei + N_EDGES;

    cudaFuncSetAttribute(update_kernel,
                         cudaFuncAttributeMaxDynamicSharedMemorySize, U_SMEM);
    cudaFuncSetAttribute(proj_pre_kernel,
                         cudaFuncAttributeMaxDynamicSharedMemorySize, PP_SMEM);

    init_kernel<<<(N_NODES * HID / 4) / 256, 256>>>();
    setup_kernel<<<SETUP_BLKS, 256>>>(dstIdx, batch, mw2, uw, mb2);
    proj_pre_kernel<<<(N_NODES + 63) / 64, 256, PP_SMEM>>>(x, npw, npb, mw1, mb1);

    int ping = 0;
    for (int l = 0; l < NLAYERS; l++) {
        const float* W1l  = mw1 + (size_t)l * (HID + EDGE_DIM) * HID;
        const float* W1el = W1l + (size_t)HID * HID;
        const float* Wul  = uw  + (size_t)l * 2 * HID * HID;
        const int hasNext = (l + 1 < NLAYERS);
        const float* W1n  = hasNext ? (W1l + (size_t)(HID + EDGE_DIM) * HID) : W1l;
        const float* B1n  = hasNext ? (mb1 + (size_t)(l + 1) * HID) : mb1;

        edge_kernel<<<N_ETILES, 256>>>(eattr, srcIdx, dstIdx, W1el);
        update_kernel<<<(N_NODES + UROWS - 1) / UROWS, 256, U_SMEM>>>(
            ping, l, Wul, ub + (size_t)l * HID,
            lg + (size_t)l * HID, lb + (size_t)l * HID,
            W1n, B1n, batch, hasNext);
        ping ^= 1;
    }

    readout_kernel<<<NGRAPHS, 128>>>(fw1, fb1, fw2, fb2, out);
}